// round 4
// baseline (speedup 1.0000x reference)
#include <cuda_runtime.h>
#include <math.h>
#include <stdint.h>

// Problem constants (shapes fixed by the dataset)
#define N_NODES 10000
#define E_EDGES 160000
#define IN_F    128
#define H1_F    512
#define H2_F    1024
#define H3_F    512
#define OUT_F   32

// ---------------------------------------------------------------------------
// Scratch (static device globals — no dynamic allocation allowed)
// ---------------------------------------------------------------------------
__device__ int   g_is64;                  // 1 if edge_index is int64
__device__ int   g_src[E_EDGES];          // clean int32 indices
__device__ int   g_dst[E_EDGES];
__device__ float g_dinv[N_NODES];
__device__ int   g_cnt[N_NODES];          // incoming edge count (no self loop)
__device__ int   g_cursor[N_NODES];       // fill cursors
__device__ int   g_rowptr[N_NODES + 1];   // CSR row pointers (by dst)
__device__ int   g_col[E_EDGES];          // CSR: src node per slot
__device__ float g_wt[E_EDGES];           // CSR: edge weight per slot
// float4 typed => guaranteed 16B alignment for vector loads/stores
__device__ float4 g_buf0[(size_t)N_NODES * H2_F / 4];
__device__ float4 g_buf1[(size_t)N_NODES * H2_F / 4];
__device__ float4 g_buf2[(size_t)N_NODES * H2_F / 4];

// ---------------------------------------------------------------------------
// Edge-index dtype detection + conversion
// int64 data has every value in [0, N). int32 data misread as int64 packs two
// random values per word -> astronomically unlikely to stay in range 128x.
// ---------------------------------------------------------------------------
__global__ void k_detect(const void* __restrict__ ei) {
    const long long* p = (const long long*)ei;
    int ok = 1;
    for (int i = 0; i < 128; i++) {
        long long v = p[i];
        if (v < 0 || v >= N_NODES) { ok = 0; break; }
    }
    g_is64 = ok;
}

__global__ void k_convert(const void* __restrict__ ei, int E) {
    int e = blockIdx.x * blockDim.x + threadIdx.x;
    if (e >= E) return;
    if (g_is64) {
        const long long* p = (const long long*)ei;
        g_src[e] = (int)p[e];
        g_dst[e] = (int)p[e + E];
    } else {
        const int* p = (const int*)ei;
        g_src[e] = p[e];
        g_dst[e] = p[e + E];
    }
}

// ---------------------------------------------------------------------------
// CSR build
// ---------------------------------------------------------------------------
__global__ void k_zero() {
    int i = blockIdx.x * blockDim.x + threadIdx.x;
    if (i < N_NODES) { g_cnt[i] = 0; g_cursor[i] = 0; }
}

__global__ void k_count(int E) {
    int e = blockIdx.x * blockDim.x + threadIdx.x;
    if (e < E) atomicAdd(&g_cnt[g_dst[e]], 1);
}

// single-block inclusive scan of g_cnt -> g_rowptr, plus dinv = rsqrt(cnt+1)
__global__ __launch_bounds__(1024)
void k_scan_dinv() {
    __shared__ int sh[1024];
    __shared__ int s_off;
    const int tid = threadIdx.x;
    if (tid == 0) s_off = 0;
    __syncthreads();
    for (int base = 0; base < N_NODES; base += 1024) {
        int i = base + tid;
        int v = (i < N_NODES) ? g_cnt[i] : 0;
        if (i < N_NODES) g_dinv[i] = rsqrtf((float)v + 1.0f); // +1 self loop
        sh[tid] = v;
        __syncthreads();
#pragma unroll
        for (int o = 1; o < 1024; o <<= 1) {
            int t = (tid >= o) ? sh[tid - o] : 0;
            __syncthreads();
            sh[tid] += t;
            __syncthreads();
        }
        int incl = sh[tid];
        int off = s_off;
        if (i < N_NODES) g_rowptr[i + 1] = off + incl;
        __syncthreads();
        if (tid == 1023) s_off = off + incl;
        __syncthreads();
    }
    if (tid == 0) g_rowptr[0] = 0;
}

__global__ void k_fill(int E) {
    int e = blockIdx.x * blockDim.x + threadIdx.x;
    if (e >= E) return;
    int s = g_src[e];
    int d = g_dst[e];
    float w = g_dinv[s] * g_dinv[d];
    int pos = g_rowptr[d] + atomicAdd(&g_cursor[d], 1);
    g_col[pos] = s;
    g_wt[pos]  = w;
}

// ---------------------------------------------------------------------------
// GEMM: C[M,N] = A[M,K] @ B[K,N], fp32, 64x64 block, 4x4 per thread
// ---------------------------------------------------------------------------
#define BM 64
#define BN 64
#define BK 16

__global__ __launch_bounds__(256)
void k_gemm(const float* __restrict__ A, const float* __restrict__ B,
            float* __restrict__ C, int M, int K, int N) {
    __shared__ float As[BK][BM + 4];
    __shared__ float Bs[BK][BN];

    const int block_row = blockIdx.y * BM;
    const int block_col = blockIdx.x * BN;
    const int tid = threadIdx.x;
    const int tr = (tid >> 4) << 2;
    const int tc = (tid & 15) << 2;

    float acc[4][4];
#pragma unroll
    for (int i = 0; i < 4; i++)
#pragma unroll
        for (int j = 0; j < 4; j++) acc[i][j] = 0.0f;

    for (int k0 = 0; k0 < K; k0 += BK) {
#pragma unroll
        for (int i = tid; i < BM * BK; i += 256) {
            int r = i >> 4;
            int c = i & (BK - 1);
            int gr = block_row + r;
            As[c][r] = (gr < M) ? A[(size_t)gr * K + (k0 + c)] : 0.0f;
        }
#pragma unroll
        for (int i = tid; i < BK * BN; i += 256) {
            int r = i >> 6;
            int c = i & (BN - 1);
            int gc = block_col + c;
            Bs[r][c] = (gc < N) ? B[(size_t)(k0 + r) * N + gc] : 0.0f;
        }
        __syncthreads();

#pragma unroll
        for (int k = 0; k < BK; ++k) {
            float a[4], b[4];
#pragma unroll
            for (int i = 0; i < 4; i++) a[i] = As[k][tr + i];
#pragma unroll
            for (int j = 0; j < 4; j++) b[j] = Bs[k][tc + j];
#pragma unroll
            for (int i = 0; i < 4; i++)
#pragma unroll
                for (int j = 0; j < 4; j++) acc[i][j] = fmaf(a[i], b[j], acc[i][j]);
        }
        __syncthreads();
    }

#pragma unroll
    for (int i = 0; i < 4; i++) {
        int gr = block_row + tr + i;
        if (gr >= M) continue;
#pragma unroll
        for (int j = 0; j < 4; j++) {
            int gc = block_col + tc + j;
            if (gc < N) C[(size_t)gr * N + gc] = acc[i][j];
        }
    }
}

// ---------------------------------------------------------------------------
// Aggregation (gather over CSR) + bias + optional ReLU. One block per node.
// out[i,:] = act( dinv[i]^2*lin[i,:] + sum_j wt[j]*lin[col[j],:] + bias )
// ---------------------------------------------------------------------------
template <int H, bool RELU>
__global__ __launch_bounds__(128)
void k_aggregate(const float4* __restrict__ lin,
                 const float*  __restrict__ bias,
                 float4* __restrict__ out) {
    constexpr int V = H / 4;                 // float4 lanes per row
    constexpr int PER = (V + 127) / 128;     // lanes per thread
    const int node = blockIdx.x;
    const int tid = threadIdx.x;

    float dii = g_dinv[node];
    float w0 = dii * dii;

    float4 acc[PER];
#pragma unroll
    for (int p = 0; p < PER; p++) {
        int idx = tid + p * 128;
        if (idx < V) {
            float4 v = lin[(size_t)node * V + idx];
            acc[p] = make_float4(v.x * w0, v.y * w0, v.z * w0, v.w * w0);
        }
    }

    __shared__ int   s_col[128];
    __shared__ float s_w[128];
    const int beg = g_rowptr[node];
    const int end = g_rowptr[node + 1];

    for (int j0 = beg; j0 < end; j0 += 128) {
        int n = min(128, end - j0);
        __syncthreads();
        if (tid < n) { s_col[tid] = g_col[j0 + tid]; s_w[tid] = g_wt[j0 + tid]; }
        __syncthreads();
        for (int j = 0; j < n; j++) {
            int s = s_col[j];
            float w = s_w[j];
            const float4* row = lin + (size_t)s * V;
#pragma unroll
            for (int p = 0; p < PER; p++) {
                int idx = tid + p * 128;
                if (idx < V) {
                    float4 v = row[idx];
                    acc[p].x = fmaf(w, v.x, acc[p].x);
                    acc[p].y = fmaf(w, v.y, acc[p].y);
                    acc[p].z = fmaf(w, v.z, acc[p].z);
                    acc[p].w = fmaf(w, v.w, acc[p].w);
                }
            }
        }
    }

#pragma unroll
    for (int p = 0; p < PER; p++) {
        int idx = tid + p * 128;
        if (idx < V) {
            float4 b = reinterpret_cast<const float4*>(bias)[idx];
            float4 r;
            r.x = acc[p].x + b.x; r.y = acc[p].y + b.y;
            r.z = acc[p].z + b.z; r.w = acc[p].w + b.w;
            if (RELU) {
                r.x = fmaxf(r.x, 0.0f); r.y = fmaxf(r.y, 0.0f);
                r.z = fmaxf(r.z, 0.0f); r.w = fmaxf(r.w, 0.0f);
            }
            out[(size_t)node * V + idx] = r;
        }
    }
}

// ---------------------------------------------------------------------------
// log_softmax over 32 cols (bias already applied), one warp per row
// ---------------------------------------------------------------------------
__global__ void k_logsoftmax(const float* __restrict__ h,
                             float* __restrict__ out) {
    int gtid = blockIdx.x * blockDim.x + threadIdx.x;
    int row = gtid >> 5;
    int lane = gtid & 31;
    if (row >= N_NODES) return;
    float v = h[(size_t)row * OUT_F + lane];
    float m = v;
#pragma unroll
    for (int o = 16; o > 0; o >>= 1)
        m = fmaxf(m, __shfl_xor_sync(0xFFFFFFFFu, m, o));
    float ex = expf(v - m);
    float s = ex;
#pragma unroll
    for (int o = 16; o > 0; o >>= 1)
        s += __shfl_xor_sync(0xFFFFFFFFu, s, o);
    out[(size_t)row * OUT_F + lane] = v - m - logf(s);
}

// ---------------------------------------------------------------------------
// Launch
// ---------------------------------------------------------------------------
static inline int cdiv(long long a, int b) { return (int)((a + b - 1) / b); }

extern "C" void kernel_launch(void* const* d_in, const int* in_sizes, int n_in,
                              void* d_out, int out_size) {
    const float* x  = (const float*)d_in[0];
    const void*  ei = d_in[1];
    const float* W1 = (const float*)d_in[2];
    const float* b1 = (const float*)d_in[3];
    const float* W2 = (const float*)d_in[4];
    const float* b2 = (const float*)d_in[5];
    const float* W3 = (const float*)d_in[6];
    const float* b3 = (const float*)d_in[7];
    const float* W4 = (const float*)d_in[8];
    const float* b4 = (const float*)d_in[9];
    float* out = (float*)d_out;

    const int E = in_sizes[1] / 2;

    float4 *buf0, *buf1, *buf2;
    cudaGetSymbolAddress((void**)&buf0, g_buf0);
    cudaGetSymbolAddress((void**)&buf1, g_buf1);
    cudaGetSymbolAddress((void**)&buf2, g_buf2);

    // --- index ingestion (dtype-agnostic) ---
    k_detect<<<1, 1>>>(ei);
    k_convert<<<cdiv(E, 256), 256>>>(ei, E);

    // --- CSR build + normalization ---
    k_zero<<<cdiv(N_NODES, 256), 256>>>();
    k_count<<<cdiv(E, 256), 256>>>(E);
    k_scan_dinv<<<1, 1024>>>();
    k_fill<<<cdiv(E, 256), 256>>>(E);

    // --- layers: lin = in @ W (buf0) ; agg+bias(+relu) -> target ---
    // L1: x[N,128] @ W1 -> 512
    {
        dim3 grid((H1_F + BN - 1) / BN, (N_NODES + BM - 1) / BM);
        k_gemm<<<grid, 256>>>(x, W1, (float*)buf0, N_NODES, IN_F, H1_F);
        k_aggregate<H1_F, true><<<N_NODES, 128>>>(buf0, b1, buf1);
    }
    // L2: 512 -> 1024
    {
        dim3 grid((H2_F + BN - 1) / BN, (N_NODES + BM - 1) / BM);
        k_gemm<<<grid, 256>>>((const float*)buf1, W2, (float*)buf0, N_NODES, H1_F, H2_F);
        k_aggregate<H2_F, true><<<N_NODES, 128>>>(buf0, b2, buf2);
    }
    // L3: 1024 -> 512
    {
        dim3 grid((H3_F + BN - 1) / BN, (N_NODES + BM - 1) / BM);
        k_gemm<<<grid, 256>>>((const float*)buf2, W3, (float*)buf0, N_NODES, H2_F, H3_F);
        k_aggregate<H3_F, true><<<N_NODES, 128>>>(buf0, b3, buf1);
    }
    // L4: 512 -> 32 (bias added in aggregate, no relu)
    {
        dim3 grid((OUT_F + BN - 1) / BN, (N_NODES + BM - 1) / BM);
        k_gemm<<<grid, 256>>>((const float*)buf1, W4, (float*)buf0, N_NODES, H3_F, OUT_F);
        k_aggregate<OUT_F, false><<<N_NODES, 128>>>(buf0, b4, buf2);
    }

    k_logsoftmax<<<cdiv((long long)N_NODES * 32, 256), 256>>>((const float*)buf2, out);
}

// round 6
// speedup vs baseline: 1.5799x; 1.5799x over previous
#include <cuda_runtime.h>
#include <cuda_bf16.h>
#include <math.h>
#include <stdint.h>

// Problem constants
#define N_NODES 10000
#define E_EDGES 160000
#define IN_F    128
#define H1_F    512
#define H2_F    1024
#define H3_F    512
#define OUT_F   32

// ===========================================================================
// Scratch (static device globals)
// ===========================================================================
__device__ int   g_is64;
__device__ int   g_src[E_EDGES];
__device__ int   g_dst[E_EDGES];
__device__ float g_dinv[N_NODES];
__device__ int   g_cnt[N_NODES];
__device__ int   g_cursor[N_NODES];
__device__ int   g_rowptr[N_NODES + 1];
__device__ int   g_col[E_EDGES];
__device__ float g_wt[E_EDGES];
__device__ float4 g_buf0[(size_t)N_NODES * H2_F / 4];
__device__ float4 g_buf1[(size_t)N_NODES * H2_F / 4];
__device__ float4 g_buf2[(size_t)N_NODES * H2_F / 4];
// bf16 split buffers (uint4-typed for 16B-aligned vector access)
__device__ uint4 g_Ahi[(size_t)N_NODES * H2_F * 2 / 16];
__device__ uint4 g_Alo[(size_t)N_NODES * H2_F * 2 / 16];
__device__ uint4 g_Bhi[(size_t)H2_F * H3_F * 2 / 16];
__device__ uint4 g_Blo[(size_t)H2_F * H3_F * 2 / 16];

// ===========================================================================
// Edge-index ingestion (dtype-agnostic)
// ===========================================================================
__global__ void k_detect(const void* __restrict__ ei) {
    const long long* p = (const long long*)ei;
    int ok = 1;
    for (int i = 0; i < 128; i++) {
        long long v = p[i];
        if (v < 0 || v >= N_NODES) { ok = 0; break; }
    }
    g_is64 = ok;
}
__global__ void k_convert(const void* __restrict__ ei, int E) {
    int e = blockIdx.x * blockDim.x + threadIdx.x;
    if (e >= E) return;
    if (g_is64) {
        const long long* p = (const long long*)ei;
        g_src[e] = (int)p[e];
        g_dst[e] = (int)p[e + E];
    } else {
        const int* p = (const int*)ei;
        g_src[e] = p[e];
        g_dst[e] = p[e + E];
    }
}

// ===========================================================================
// CSR build
// ===========================================================================
__global__ void k_zero() {
    int i = blockIdx.x * blockDim.x + threadIdx.x;
    if (i < N_NODES) { g_cnt[i] = 0; g_cursor[i] = 0; }
}
__global__ void k_count(int E) {
    int e = blockIdx.x * blockDim.x + threadIdx.x;
    if (e < E) atomicAdd(&g_cnt[g_dst[e]], 1);
}
__global__ __launch_bounds__(1024)
void k_scan_dinv() {
    __shared__ int sh[1024];
    __shared__ int s_off;
    const int tid = threadIdx.x;
    if (tid == 0) s_off = 0;
    __syncthreads();
    for (int base = 0; base < N_NODES; base += 1024) {
        int i = base + tid;
        int v = (i < N_NODES) ? g_cnt[i] : 0;
        if (i < N_NODES) g_dinv[i] = rsqrtf((float)v + 1.0f);
        sh[tid] = v;
        __syncthreads();
#pragma unroll
        for (int o = 1; o < 1024; o <<= 1) {
            int t = (tid >= o) ? sh[tid - o] : 0;
            __syncthreads();
            sh[tid] += t;
            __syncthreads();
        }
        int incl = sh[tid];
        int off = s_off;
        if (i < N_NODES) g_rowptr[i + 1] = off + incl;
        __syncthreads();
        if (tid == 1023) s_off = off + incl;
        __syncthreads();
    }
    if (tid == 0) g_rowptr[0] = 0;
}
__global__ void k_fill(int E) {
    int e = blockIdx.x * blockDim.x + threadIdx.x;
    if (e >= E) return;
    int s = g_src[e];
    int d = g_dst[e];
    float w = g_dinv[s] * g_dinv[d];
    int pos = g_rowptr[d] + atomicAdd(&g_cursor[d], 1);
    g_col[pos] = s;
    g_wt[pos]  = w;
}

// ===========================================================================
// fp32 -> (hi, lo) bf16 split, elementwise over float4 lanes
// ===========================================================================
__global__ void k_split(const float4* __restrict__ a,
                        __nv_bfloat162* __restrict__ hi,
                        __nv_bfloat162* __restrict__ lo, int total4) {
    int idx = blockIdx.x * blockDim.x + threadIdx.x;
    if (idx >= total4) return;
    float4 v = a[idx];
    __nv_bfloat16 h0 = __float2bfloat16(v.x);
    __nv_bfloat16 h1 = __float2bfloat16(v.y);
    __nv_bfloat16 h2 = __float2bfloat16(v.z);
    __nv_bfloat16 h3 = __float2bfloat16(v.w);
    __nv_bfloat16 l0 = __float2bfloat16(v.x - __bfloat162float(h0));
    __nv_bfloat16 l1 = __float2bfloat16(v.y - __bfloat162float(h1));
    __nv_bfloat16 l2 = __float2bfloat16(v.z - __bfloat162float(h2));
    __nv_bfloat16 l3 = __float2bfloat16(v.w - __bfloat162float(h3));
    __nv_bfloat162 a01; a01.x = h0; a01.y = h1;
    __nv_bfloat162 a23; a23.x = h2; a23.y = h3;
    __nv_bfloat162 b01; b01.x = l0; b01.y = l1;
    __nv_bfloat162 b23; b23.x = l2; b23.y = l3;
    hi[idx * 2]     = a01;
    hi[idx * 2 + 1] = a23;
    lo[idx * 2]     = b01;
    lo[idx * 2 + 1] = b23;
}

// W [K,N] fp32 -> Wt hi/lo [N,K] bf16 (transpose + split), 32x32 tiles
__global__ __launch_bounds__(256)
void k_splitT(const float* __restrict__ W,
              __nv_bfloat16* __restrict__ hi,
              __nv_bfloat16* __restrict__ lo, int K, int N) {
    __shared__ float t[32][33];
    int k0 = blockIdx.x * 32, n0 = blockIdx.y * 32;
    int tx = threadIdx.x, ty = threadIdx.y;   // blockDim (32, 8)
#pragma unroll
    for (int j = 0; j < 4; j++)
        t[ty + j * 8][tx] = W[(size_t)(k0 + ty + j * 8) * N + (n0 + tx)];
    __syncthreads();
#pragma unroll
    for (int j = 0; j < 4; j++) {
        float v = t[tx][ty + j * 8];
        int n = n0 + ty + j * 8;
        int k = k0 + tx;
        __nv_bfloat16 h = __float2bfloat16(v);
        __nv_bfloat16 l = __float2bfloat16(v - __bfloat162float(h));
        hi[(size_t)n * K + k] = h;
        lo[(size_t)n * K + k] = l;
    }
}

// ===========================================================================
// mma.sync bf16 split-precision GEMM: C[M,N] = A[M,K] @ B[K,N]
//   A as Ahi/Alo [M,K] bf16 row-major, B as Bhi/Blo [N,K] bf16 (pre-T).
//   CTA = 128x128 tile, 8 warps (4m x 2n), warp tile 32x64 = 2x8 m16n8k16.
//   fp32 register accumulators; 3 passes: hi*hi + hi*lo + lo*hi.
// ===========================================================================
#define KC 32                        // K-chunk in SMEM
#define SROW 40                      // padded row stride in bf16 (80 bytes)

__device__ __forceinline__ void mma16816(float* c, const uint32_t* a,
                                         const uint32_t* b) {
    asm volatile(
        "mma.sync.aligned.m16n8k16.row.col.f32.bf16.bf16.f32 "
        "{%0,%1,%2,%3}, {%4,%5,%6,%7}, {%8,%9}, {%0,%1,%2,%3};"
        : "+f"(c[0]), "+f"(c[1]), "+f"(c[2]), "+f"(c[3])
        : "r"(a[0]), "r"(a[1]), "r"(a[2]), "r"(a[3]), "r"(b[0]), "r"(b[1]));
}

template <bool BIASRELU>
__global__ __launch_bounds__(256)
void k_gemm_mma(const uint4* __restrict__ Ahi, const uint4* __restrict__ Alo,
                const uint4* __restrict__ Bhi, const uint4* __restrict__ Blo,
                const float* __restrict__ bias, float* __restrict__ C,
                int M, int K, int Ncols) {
    __shared__ __align__(16) __nv_bfloat16 sAhi[128 * SROW];
    __shared__ __align__(16) __nv_bfloat16 sAlo[128 * SROW];
    __shared__ __align__(16) __nv_bfloat16 sBhi[128 * SROW];
    __shared__ __align__(16) __nv_bfloat16 sBlo[128 * SROW];

    const int tid   = threadIdx.x;
    const int lane  = tid & 31;
    const int wid   = tid >> 5;
    const int warp_m = wid & 3;      // 0..3 -> 32 rows each
    const int warp_n = wid >> 2;     // 0..1 -> 64 cols each
    const int g   = lane >> 2;       // group 0..7
    const int tig = lane & 3;        // thread-in-group 0..3

    const int mrow0 = blockIdx.y * 128;
    const int ncol0 = blockIdx.x * 128;
    const int KU = K >> 3;           // uint4 per bf16 row
    const int nChunks = K / KC;

    float acc[2][8][4];
#pragma unroll
    for (int i = 0; i < 2; i++)
#pragma unroll
        for (int j = 0; j < 8; j++)
#pragma unroll
            for (int q = 0; q < 4; q++) acc[i][j][q] = 0.0f;

    for (int it = 0; it < nChunks; it++) {
        const int ku0 = it * (KC / 8);
        // Load A/B hi+lo chunk tiles [128 x 32 bf16] with 80B padded rows
#pragma unroll
        for (int q = tid; q < 512; q += 256) {
            int row = q >> 2;
            int cb = q & 3;
            int so = row * SROW + cb * 8;           // bf16 offset (16B step)
            uint4 vh = make_uint4(0, 0, 0, 0), vl = vh;
            int gm = mrow0 + row;
            if (gm < M) {
                size_t ab = (size_t)gm * KU + ku0 + cb;
                vh = Ahi[ab];
                vl = Alo[ab];
            }
            *(uint4*)(sAhi + so) = vh;
            *(uint4*)(sAlo + so) = vl;
            size_t bb = (size_t)(ncol0 + row) * KU + ku0 + cb;
            *(uint4*)(sBhi + so) = Bhi[bb];
            *(uint4*)(sBlo + so) = Blo[bb];
        }
        __syncthreads();

#pragma unroll
        for (int ks = 0; ks < KC / 16; ks++) {
            const int k0 = ks * 16;
            // A fragments (2 m-tiles, hi+lo)
            uint32_t ah[2][4], al[2][4];
#pragma unroll
            for (int mt = 0; mt < 2; mt++) {
                int r0 = warp_m * 32 + mt * 16 + g;
                int c0 = k0 + tig * 2;
                ah[mt][0] = *(const uint32_t*)(sAhi + r0 * SROW + c0);
                ah[mt][1] = *(const uint32_t*)(sAhi + (r0 + 8) * SROW + c0);
                ah[mt][2] = *(const uint32_t*)(sAhi + r0 * SROW + c0 + 8);
                ah[mt][3] = *(const uint32_t*)(sAhi + (r0 + 8) * SROW + c0 + 8);
                al[mt][0] = *(const uint32_t*)(sAlo + r0 * SROW + c0);
                al[mt][1] = *(const uint32_t*)(sAlo + (r0 + 8) * SROW + c0);
                al[mt][2] = *(const uint32_t*)(sAlo + r0 * SROW + c0 + 8);
                al[mt][3] = *(const uint32_t*)(sAlo + (r0 + 8) * SROW + c0 + 8);
            }
            // B fragments (8 n-tiles, hi+lo)
            uint32_t bh[8][2], bl[8][2];
#pragma unroll
            for (int nt = 0; nt < 8; nt++) {
                int r0 = warp_n * 64 + nt * 8 + g;
                int c0 = k0 + tig * 2;
                bh[nt][0] = *(const uint32_t*)(sBhi + r0 * SROW + c0);
                bh[nt][1] = *(const uint32_t*)(sBhi + r0 * SROW + c0 + 8);
                bl[nt][0] = *(const uint32_t*)(sBlo + r0 * SROW + c0);
                bl[nt][1] = *(const uint32_t*)(sBlo + r0 * SROW + c0 + 8);
            }
#pragma unroll
            for (int mt = 0; mt < 2; mt++)
#pragma unroll
                for (int nt = 0; nt < 8; nt++) {
                    mma16816(acc[mt][nt], ah[mt], bh[nt]);   // hi*hi
                    mma16816(acc[mt][nt], ah[mt], bl[nt]);   // hi*lo
                    mma16816(acc[mt][nt], al[mt], bh[nt]);   // lo*hi
                }
        }
        __syncthreads();
    }

    // Epilogue: c0,c1 -> row g; c2,c3 -> row g+8; cols tig*2, tig*2+1
#pragma unroll
    for (int mt = 0; mt < 2; mt++) {
        int rbase = mrow0 + warp_m * 32 + mt * 16;
#pragma unroll
        for (int nt = 0; nt < 8; nt++) {
            int col = ncol0 + warp_n * 64 + nt * 8 + tig * 2;
            float b0 = 0.0f, b1 = 0.0f;
            if (BIASRELU) { b0 = bias[col]; b1 = bias[col + 1]; }
            int r0 = rbase + g;
            if (r0 < M) {
                float v0 = acc[mt][nt][0] + b0;
                float v1 = acc[mt][nt][1] + b1;
                if (BIASRELU) { v0 = fmaxf(v0, 0.0f); v1 = fmaxf(v1, 0.0f); }
                float2 o = make_float2(v0, v1);
                *(float2*)(C + (size_t)r0 * Ncols + col) = o;
            }
            int r1 = rbase + g + 8;
            if (r1 < M) {
                float v0 = acc[mt][nt][2] + b0;
                float v1 = acc[mt][nt][3] + b1;
                if (BIASRELU) { v0 = fmaxf(v0, 0.0f); v1 = fmaxf(v1, 0.0f); }
                float2 o = make_float2(v0, v1);
                *(float2*)(C + (size_t)r1 * Ncols + col) = o;
            }
        }
    }
}

// ===========================================================================
// fp32 GEMM (64x64) — kept for the tiny L4 (N=32)
// ===========================================================================
#define BM 64
#define BN 64
#define BK 16
__global__ __launch_bounds__(256)
void k_gemm(const float* __restrict__ A, const float* __restrict__ B,
            float* __restrict__ C, int M, int K, int N) {
    __shared__ float As[BK][BM + 4];
    __shared__ float Bs[BK][BN];
    const int block_row = blockIdx.y * BM;
    const int block_col = blockIdx.x * BN;
    const int tid = threadIdx.x;
    const int tr = (tid >> 4) << 2;
    const int tc = (tid & 15) << 2;
    float acc[4][4];
#pragma unroll
    for (int i = 0; i < 4; i++)
#pragma unroll
        for (int j = 0; j < 4; j++) acc[i][j] = 0.0f;
    for (int k0 = 0; k0 < K; k0 += BK) {
#pragma unroll
        for (int i = tid; i < BM * BK; i += 256) {
            int r = i >> 4, c = i & (BK - 1);
            int gr = block_row + r;
            As[c][r] = (gr < M) ? A[(size_t)gr * K + (k0 + c)] : 0.0f;
        }
#pragma unroll
        for (int i = tid; i < BK * BN; i += 256) {
            int r = i >> 6, c = i & (BN - 1);
            int gc = block_col + c;
            Bs[r][c] = (gc < N) ? B[(size_t)(k0 + r) * N + gc] : 0.0f;
        }
        __syncthreads();
#pragma unroll
        for (int k = 0; k < BK; ++k) {
            float a[4], b[4];
#pragma unroll
            for (int i = 0; i < 4; i++) a[i] = As[k][tr + i];
#pragma unroll
            for (int j = 0; j < 4; j++) b[j] = Bs[k][tc + j];
#pragma unroll
            for (int i = 0; i < 4; i++)
#pragma unroll
                for (int j = 0; j < 4; j++) acc[i][j] = fmaf(a[i], b[j], acc[i][j]);
        }
        __syncthreads();
    }
#pragma unroll
    for (int i = 0; i < 4; i++) {
        int gr = block_row + tr + i;
        if (gr >= M) continue;
#pragma unroll
        for (int j = 0; j < 4; j++) {
            int gc = block_col + tc + j;
            if (gc < N) C[(size_t)gr * N + gc] = acc[i][j];
        }
    }
}

// ===========================================================================
// Aggregation (gather over CSR), block per node
// ===========================================================================
template <int H, bool RELU, bool HASBIAS>
__global__ __launch_bounds__(128)
void k_aggregate(const float4* __restrict__ lin,
                 const float*  __restrict__ bias,
                 float4* __restrict__ out) {
    constexpr int V = H / 4;
    constexpr int PER = (V + 127) / 128;
    const int node = blockIdx.x;
    const int tid = threadIdx.x;
    float dii = g_dinv[node];
    float w0 = dii * dii;

    float4 acc[PER];
#pragma unroll
    for (int p = 0; p < PER; p++) {
        int idx = tid + p * 128;
        if (idx < V) {
            float4 v = lin[(size_t)node * V + idx];
            acc[p] = make_float4(v.x * w0, v.y * w0, v.z * w0, v.w * w0);
        }
    }
    __shared__ int   s_col[128];
    __shared__ float s_w[128];
    const int beg = g_rowptr[node];
    const int end = g_rowptr[node + 1];
    for (int j0 = beg; j0 < end; j0 += 128) {
        int n = min(128, end - j0);
        __syncthreads();
        if (tid < n) { s_col[tid] = g_col[j0 + tid]; s_w[tid] = g_wt[j0 + tid]; }
        __syncthreads();
        for (int j = 0; j < n; j++) {
            int s = s_col[j];
            float w = s_w[j];
            const float4* row = lin + (size_t)s * V;
#pragma unroll
            for (int p = 0; p < PER; p++) {
                int idx = tid + p * 128;
                if (idx < V) {
                    float4 v = row[idx];
                    acc[p].x = fmaf(w, v.x, acc[p].x);
                    acc[p].y = fmaf(w, v.y, acc[p].y);
                    acc[p].z = fmaf(w, v.z, acc[p].z);
                    acc[p].w = fmaf(w, v.w, acc[p].w);
                }
            }
        }
    }
#pragma unroll
    for (int p = 0; p < PER; p++) {
        int idx = tid + p * 128;
        if (idx < V) {
            float4 r = acc[p];
            if (HASBIAS) {
                float4 b = reinterpret_cast<const float4*>(bias)[idx];
                r.x += b.x; r.y += b.y; r.z += b.z; r.w += b.w;
            }
            if (RELU) {
                r.x = fmaxf(r.x, 0.0f); r.y = fmaxf(r.y, 0.0f);
                r.z = fmaxf(r.z, 0.0f); r.w = fmaxf(r.w, 0.0f);
            }
            out[(size_t)node * V + idx] = r;
        }
    }
}

// H=128 pre-aggregation: one warp per node (lane = one float4), 8 nodes/block
__global__ __launch_bounds__(256)
void k_agg128(const float4* __restrict__ lin, float4* __restrict__ out) {
    int node = blockIdx.x * 8 + threadIdx.y;
    if (node >= N_NODES) return;
    int lane = threadIdx.x;
    float dii = g_dinv[node];
    float w0 = dii * dii;
    float4 a = lin[(size_t)node * 32 + lane];
    a.x *= w0; a.y *= w0; a.z *= w0; a.w *= w0;
    int beg = g_rowptr[node], end = g_rowptr[node + 1];
    for (int j = beg; j < end; j++) {
        int s = g_col[j];
        float w = g_wt[j];
        float4 v = lin[(size_t)s * 32 + lane];
        a.x = fmaf(w, v.x, a.x); a.y = fmaf(w, v.y, a.y);
        a.z = fmaf(w, v.z, a.z); a.w = fmaf(w, v.w, a.w);
    }
    out[(size_t)node * 32 + lane] = a;
}

// ===========================================================================
// log_softmax over 32 cols (bias pre-applied), one warp per row
// ===========================================================================
__global__ void k_logsoftmax(const float* __restrict__ h,
                             float* __restrict__ out) {
    int gtid = blockIdx.x * blockDim.x + threadIdx.x;
    int row = gtid >> 5;
    int lane = gtid & 31;
    if (row >= N_NODES) return;
    float v = h[(size_t)row * OUT_F + lane];
    float m = v;
#pragma unroll
    for (int o = 16; o > 0; o >>= 1)
        m = fmaxf(m, __shfl_xor_sync(0xFFFFFFFFu, m, o));
    float ex = expf(v - m);
    float s = ex;
#pragma unroll
    for (int o = 16; o > 0; o >>= 1)
        s += __shfl_xor_sync(0xFFFFFFFFu, s, o);
    out[(size_t)row * OUT_F + lane] = v - m - logf(s);
}

// ===========================================================================
// Launch
// ===========================================================================
static inline int cdiv(long long a, int b) { return (int)((a + b - 1) / b); }

extern "C" void kernel_launch(void* const* d_in, const int* in_sizes, int n_in,
                              void* d_out, int out_size) {
    const float* x  = (const float*)d_in[0];
    const void*  ei = d_in[1];
    const float* W1 = (const float*)d_in[2];
    const float* b1 = (const float*)d_in[3];
    const float* W2 = (const float*)d_in[4];
    const float* b2 = (const float*)d_in[5];
    const float* W3 = (const float*)d_in[6];
    const float* b3 = (const float*)d_in[7];
    const float* W4 = (const float*)d_in[8];
    const float* b4 = (const float*)d_in[9];
    float* out = (float*)d_out;

    const int E = in_sizes[1] / 2;

    float4 *buf0, *buf1, *buf2;
    uint4 *Ahi, *Alo, *Bhi, *Blo;
    cudaGetSymbolAddress((void**)&buf0, g_buf0);
    cudaGetSymbolAddress((void**)&buf1, g_buf1);
    cudaGetSymbolAddress((void**)&buf2, g_buf2);
    cudaGetSymbolAddress((void**)&Ahi, g_Ahi);
    cudaGetSymbolAddress((void**)&Alo, g_Alo);
    cudaGetSymbolAddress((void**)&Bhi, g_Bhi);
    cudaGetSymbolAddress((void**)&Blo, g_Blo);

    const int MT = cdiv(N_NODES, 128);   // 79 M-tiles
    dim3 agg8(32, 8);

    // --- index ingestion + CSR ---
    k_detect<<<1, 1>>>(ei);
    k_convert<<<cdiv(E, 256), 256>>>(ei, E);
    k_zero<<<cdiv(N_NODES, 256), 256>>>();
    k_count<<<cdiv(E, 256), 256>>>(E);
    k_scan_dinv<<<1, 1024>>>();
    k_fill<<<cdiv(E, 256), 256>>>(E);

    // --- L1: pre-agg (128) -> split -> MMA GEMM (K=128, N=512) + bias+relu ---
    k_agg128<<<cdiv(N_NODES, 8), agg8>>>((const float4*)x, buf0);
    k_split<<<cdiv((long long)N_NODES * IN_F / 4, 256), 256>>>(
        buf0, (__nv_bfloat162*)Ahi, (__nv_bfloat162*)Alo, N_NODES * IN_F / 4);
    k_splitT<<<dim3(IN_F / 32, H1_F / 32), dim3(32, 8)>>>(
        W1, (__nv_bfloat16*)Bhi, (__nv_bfloat16*)Blo, IN_F, H1_F);
    k_gemm_mma<true><<<dim3(H1_F / 128, MT), 256>>>(
        Ahi, Alo, Bhi, Blo, b1, (float*)buf1, N_NODES, IN_F, H1_F);

    // --- L2: pre-agg (512) -> split -> MMA GEMM (K=512, N=1024) + bias+relu ---
    k_aggregate<H1_F, false, false><<<N_NODES, 128>>>(buf1, nullptr, buf0);
    k_split<<<cdiv((long long)N_NODES * H1_F / 4, 256), 256>>>(
        buf0, (__nv_bfloat162*)Ahi, (__nv_bfloat162*)Alo, N_NODES * H1_F / 4);
    k_splitT<<<dim3(H1_F / 32, H2_F / 32), dim3(32, 8)>>>(
        W2, (__nv_bfloat16*)Bhi, (__nv_bfloat16*)Blo, H1_F, H2_F);
    k_gemm_mma<true><<<dim3(H2_F / 128, MT), 256>>>(
        Ahi, Alo, Bhi, Blo, b2, (float*)buf2, N_NODES, H1_F, H2_F);

    // --- L3: split -> MMA GEMM (K=1024, N=512) -> post-agg + bias + relu ---
    k_split<<<cdiv((long long)N_NODES * H2_F / 4, 256), 256>>>(
        buf2, (__nv_bfloat162*)Ahi, (__nv_bfloat162*)Alo, N_NODES * H2_F / 4);
    k_splitT<<<dim3(H2_F / 32, H3_F / 32), dim3(32, 8)>>>(
        W3, (__nv_bfloat16*)Bhi, (__nv_bfloat16*)Blo, H2_F, H3_F);
    k_gemm_mma<false><<<dim3(H3_F / 128, MT), 256>>>(
        Ahi, Alo, Bhi, Blo, nullptr, (float*)buf0, N_NODES, H2_F, H3_F);
    k_aggregate<H3_F, true, true><<<N_NODES, 128>>>(buf0, b3, buf1);

    // --- L4: fp32 GEMM (N=32) -> post-agg + bias -> log_softmax ---
    {
        dim3 grid((OUT_F + BN - 1) / BN, (N_NODES + BM - 1) / BM);
        k_gemm<<<grid, 256>>>((const float*)buf1, W4, (float*)buf0,
                              N_NODES, H3_F, OUT_F);
    }
    k_aggregate<OUT_F, false, true><<<N_NODES, 128>>>(buf0, b4, buf2);
    k_logsoftmax<<<cdiv((long long)N_NODES * 32, 256), 256>>>((const float*)buf2, out);
}

// round 7
// speedup vs baseline: 1.9668x; 1.2449x over previous
#include <cuda_runtime.h>
#include <cuda_bf16.h>
#include <math.h>
#include <stdint.h>

#define N_NODES 10000
#define E_EDGES 160000
#define IN_F    128
#define H1_F    512
#define H2_F    1024
#define H3_F    512
#define OUT_F   32

// Weight-transpose buffer offsets (bf16 elements)
#define W1T_OFF 0
#define W2T_OFF (IN_F * H1_F)                    // 65536
#define W3T_OFF (W2T_OFF + H1_F * H2_F)          // 589824
#define WT_TOTAL (W3T_OFF + H2_F * H3_F)         // 1114112

// ===========================================================================
// Scratch (static device globals)
// ===========================================================================
__device__ int   g_is64;
__device__ int   g_src[E_EDGES];
__device__ int   g_dst[E_EDGES];
__device__ float g_dinv[N_NODES];
__device__ int   g_cnt[N_NODES];
__device__ int   g_cursor[N_NODES];
__device__ int   g_rowptr[N_NODES + 1];
__device__ int   g_col[E_EDGES];
__device__ float g_wt[E_EDGES];
__device__ float4 g_buf0[(size_t)N_NODES * H2_F / 4];
__device__ float4 g_buf1[(size_t)N_NODES * H2_F / 4];
__device__ uint4 g_Ahi[(size_t)N_NODES * H2_F * 2 / 16];   // A for L3 (and L1)
__device__ uint4 g_Alo[(size_t)N_NODES * H2_F * 2 / 16];
__device__ uint4 g_A2hi[(size_t)N_NODES * H1_F * 2 / 16];  // A for L2
__device__ uint4 g_A2lo[(size_t)N_NODES * H1_F * 2 / 16];
__device__ uint4 g_Bhi[(WT_TOTAL * 2 + 15) / 16];
__device__ uint4 g_Blo[(WT_TOTAL * 2 + 15) / 16];

// ===========================================================================
// helpers
// ===========================================================================
__device__ __forceinline__ uint32_t smem_to_u32(const void* p) {
    uint32_t a;
    asm("{ .reg .u64 t; cvta.to.shared.u64 t, %1; cvt.u32.u64 %0, t; }"
        : "=r"(a) : "l"(p));
    return a;
}
__device__ __forceinline__ void cp_async16(uint32_t s, const void* g) {
    asm volatile("cp.async.cg.shared.global [%0], [%1], 16;"
                 :: "r"(s), "l"(__cvta_generic_to_global(g)) : "memory");
}
__device__ __forceinline__ void cp_commit() {
    asm volatile("cp.async.commit_group;" ::: "memory");
}
template <int NN>
__device__ __forceinline__ void cp_wait() {
    asm volatile("cp.async.wait_group %0;" :: "n"(NN) : "memory");
}
__device__ __forceinline__ void mma16816(float* c, const uint32_t* a,
                                         const uint32_t* b) {
    asm volatile(
        "mma.sync.aligned.m16n8k16.row.col.f32.bf16.bf16.f32 "
        "{%0,%1,%2,%3}, {%4,%5,%6,%7}, {%8,%9}, {%0,%1,%2,%3};"
        : "+f"(c[0]), "+f"(c[1]), "+f"(c[2]), "+f"(c[3])
        : "r"(a[0]), "r"(a[1]), "r"(a[2]), "r"(a[3]), "r"(b[0]), "r"(b[1]));
}
__device__ __forceinline__ void split2(float v0, float v1,
                                       __nv_bfloat162& h, __nv_bfloat162& l) {
    __nv_bfloat16 h0 = __float2bfloat16(v0);
    __nv_bfloat16 h1 = __float2bfloat16(v1);
    h.x = h0; h.y = h1;
    l.x = __float2bfloat16(v0 - __bfloat162float(h0));
    l.y = __float2bfloat16(v1 - __bfloat162float(h1));
}

// ===========================================================================
// CSR chain (4 kernels)
// ===========================================================================
__global__ void k_zero_detect(const void* __restrict__ ei) {
    int i = blockIdx.x * blockDim.x + threadIdx.x;
    if (i < N_NODES) { g_cnt[i] = 0; g_cursor[i] = 0; }
    if (blockIdx.x == 0 && threadIdx.x == 0) {
        const long long* p = (const long long*)ei;
        int ok = 1;
        for (int q = 0; q < 128; q++) {
            long long v = p[q];
            if (v < 0 || v >= N_NODES) { ok = 0; break; }
        }
        g_is64 = ok;
    }
}
__global__ void k_convert_count(const void* __restrict__ ei, int E) {
    int e = blockIdx.x * blockDim.x + threadIdx.x;
    if (e >= E) return;
    int s, d;
    if (g_is64) {
        const long long* p = (const long long*)ei;
        s = (int)p[e]; d = (int)p[e + E];
    } else {
        const int* p = (const int*)ei;
        s = p[e]; d = p[e + E];
    }
    g_src[e] = s; g_dst[e] = d;
    atomicAdd(&g_cnt[d], 1);
}
__global__ __launch_bounds__(1024)
void k_scan_dinv() {
    __shared__ int sh[1024];
    __shared__ int s_off;
    const int tid = threadIdx.x;
    if (tid == 0) s_off = 0;
    __syncthreads();
    for (int base = 0; base < N_NODES; base += 1024) {
        int i = base + tid;
        int v = (i < N_NODES) ? g_cnt[i] : 0;
        if (i < N_NODES) g_dinv[i] = rsqrtf((float)v + 1.0f);
        sh[tid] = v;
        __syncthreads();
#pragma unroll
        for (int o = 1; o < 1024; o <<= 1) {
            int t = (tid >= o) ? sh[tid - o] : 0;
            __syncthreads();
            sh[tid] += t;
            __syncthreads();
        }
        int incl = sh[tid];
        int off = s_off;
        if (i < N_NODES) g_rowptr[i + 1] = off + incl;
        __syncthreads();
        if (tid == 1023) s_off = off + incl;
        __syncthreads();
    }
    if (tid == 0) g_rowptr[0] = 0;
}
__global__ void k_fill(int E) {
    int e = blockIdx.x * blockDim.x + threadIdx.x;
    if (e >= E) return;
    int s = g_src[e];
    int d = g_dst[e];
    float w = g_dinv[s] * g_dinv[d];
    int pos = g_rowptr[d] + atomicAdd(&g_cursor[d], 1);
    g_col[pos] = s;
    g_wt[pos]  = w;
}

// ===========================================================================
// All-weights transpose + split: W[K,N] fp32 -> [N,K] bf16 hi/lo at offset
// ===========================================================================
__global__ __launch_bounds__(256)
void k_splitT_all(const float* __restrict__ W1, const float* __restrict__ W2,
                  const float* __restrict__ W3,
                  __nv_bfloat16* __restrict__ hi, __nv_bfloat16* __restrict__ lo) {
    const float* W; int K, N; size_t off;
    int b = blockIdx.x;
    if (b < 64)       { W = W1; K = IN_F; N = H1_F; off = W1T_OFF; }
    else if (b < 576) { b -= 64;  W = W2; K = H1_F; N = H2_F; off = W2T_OFF; }
    else              { b -= 576; W = W3; K = H2_F; N = H3_F; off = W3T_OFF; }
    int KT = K / 32;
    int k0 = (b % KT) * 32, n0 = (b / KT) * 32;

    __shared__ float t[32][33];
    int tx = threadIdx.x, ty = threadIdx.y;   // (32, 8)
#pragma unroll
    for (int j = 0; j < 4; j++)
        t[ty + j * 8][tx] = W[(size_t)(k0 + ty + j * 8) * N + (n0 + tx)];
    __syncthreads();
#pragma unroll
    for (int j = 0; j < 4; j++) {
        float v = t[tx][ty + j * 8];
        int n = n0 + ty + j * 8;
        int k = k0 + tx;
        __nv_bfloat16 h = __float2bfloat16(v);
        __nv_bfloat16 l = __float2bfloat16(v - __bfloat162float(h));
        hi[off + (size_t)n * K + k] = h;
        lo[off + (size_t)n * K + k] = l;
    }
}

// ===========================================================================
// mma.sync bf16 split GEMM with cp.async 2-stage pipeline.
// C[M,N] = A[M,K] @ B[K,N]; A hi/lo [M,K] bf16, B hi/lo [N,K] bf16 (pre-T).
// CTA 128x128, 8 warps 4mx2n, warp 32x64. 3 passes hh+hl+lh, fp32 acc.
// EPI: 0 = bias+relu fp32, 1 = bias+relu split->bf16 hi/lo, 2 = raw fp32
// ===========================================================================
#define KC 32
#define SROW 40                      // bf16 row stride (80 B, 16B-aligned)
#define TILE_B (128 * SROW * 2)      // 10240 B per tile
#define STAGE_B (4 * TILE_B)         // 40960 B per stage
#define GEMM_SMEM (2 * STAGE_B)      // 81920 B

template <int EPI>
__global__ __launch_bounds__(256)
void k_gemm_mma(const uint4* __restrict__ Ahi, const uint4* __restrict__ Alo,
                const __nv_bfloat16* __restrict__ Bhi,
                const __nv_bfloat16* __restrict__ Blo,
                const float* __restrict__ bias, float* __restrict__ C,
                __nv_bfloat162* __restrict__ Ohi, __nv_bfloat162* __restrict__ Olo,
                int M, int K, int Ncols) {
    extern __shared__ char sm[];
    const uint32_t smb = smem_to_u32(sm);
    const int tid = threadIdx.x;
    const int lane = tid & 31;
    const int wid = tid >> 5;
    const int warp_m = wid & 3;
    const int warp_n = wid >> 2;
    const int g = lane >> 2;
    const int tig = lane & 3;
    const int mrow0 = blockIdx.y * 128;
    const int ncol0 = blockIdx.x * 128;
    const int KU = K >> 3;
    const int nChunks = K / KC;

    float acc[2][8][4];
#pragma unroll
    for (int i = 0; i < 2; i++)
#pragma unroll
        for (int j = 0; j < 8; j++)
#pragma unroll
            for (int q = 0; q < 4; q++) acc[i][j][q] = 0.0f;

    // loader: stage st gets chunk it
    auto load_chunk = [&](int it, int st) {
        const int ku0 = it * (KC / 8);
        const uint32_t sb = smb + st * STAGE_B;
#pragma unroll
        for (int q = tid; q < 512; q += 256) {
            int row = q >> 2;
            int cb = q & 3;
            uint32_t so = (uint32_t)(row * 80 + cb * 16);
            int gm = mrow0 + row;
            if (gm < M) {
                size_t ab = (size_t)gm * KU + ku0 + cb;
                cp_async16(sb + so, Ahi + ab);
                cp_async16(sb + TILE_B + so, Alo + ab);
            } else {
                *(uint4*)(sm + st * STAGE_B + so) = make_uint4(0, 0, 0, 0);
                *(uint4*)(sm + st * STAGE_B + TILE_B + so) = make_uint4(0, 0, 0, 0);
            }
            size_t bb = (size_t)(ncol0 + row) * K + it * KC + cb * 8;
            cp_async16(sb + 2 * TILE_B + so, Bhi + bb);
            cp_async16(sb + 3 * TILE_B + so, Blo + bb);
        }
        cp_commit();
    };

    load_chunk(0, 0);
    for (int it = 0; it < nChunks; it++) {
        const int cur = it & 1;
        if (it + 1 < nChunks) {
            load_chunk(it + 1, cur ^ 1);
            cp_wait<1>();
        } else {
            cp_wait<0>();
        }
        __syncthreads();

        const __nv_bfloat16* sAhi = (const __nv_bfloat16*)(sm + cur * STAGE_B);
        const __nv_bfloat16* sAlo = (const __nv_bfloat16*)(sm + cur * STAGE_B + TILE_B);
        const __nv_bfloat16* sBhi = (const __nv_bfloat16*)(sm + cur * STAGE_B + 2 * TILE_B);
        const __nv_bfloat16* sBlo = (const __nv_bfloat16*)(sm + cur * STAGE_B + 3 * TILE_B);

#pragma unroll
        for (int ks = 0; ks < KC / 16; ks++) {
            const int k0 = ks * 16;
            uint32_t ah[2][4], al[2][4];
#pragma unroll
            for (int mt = 0; mt < 2; mt++) {
                int r0 = warp_m * 32 + mt * 16 + g;
                int c0 = k0 + tig * 2;
                ah[mt][0] = *(const uint32_t*)(sAhi + r0 * SROW + c0);
                ah[mt][1] = *(const uint32_t*)(sAhi + (r0 + 8) * SROW + c0);
                ah[mt][2] = *(const uint32_t*)(sAhi + r0 * SROW + c0 + 8);
                ah[mt][3] = *(const uint32_t*)(sAhi + (r0 + 8) * SROW + c0 + 8);
                al[mt][0] = *(const uint32_t*)(sAlo + r0 * SROW + c0);
                al[mt][1] = *(const uint32_t*)(sAlo + (r0 + 8) * SROW + c0);
                al[mt][2] = *(const uint32_t*)(sAlo + r0 * SROW + c0 + 8);
                al[mt][3] = *(const uint32_t*)(sAlo + (r0 + 8) * SROW + c0 + 8);
            }
            uint32_t bh[8][2], bl[8][2];
#pragma unroll
            for (int nt = 0; nt < 8; nt++) {
                int r0 = warp_n * 64 + nt * 8 + g;
                int c0 = k0 + tig * 2;
                bh[nt][0] = *(const uint32_t*)(sBhi + r0 * SROW + c0);
                bh[nt][1] = *(const uint32_t*)(sBhi + r0 * SROW + c0 + 8);
                bl[nt][0] = *(const uint32_t*)(sBlo + r0 * SROW + c0);
                bl[nt][1] = *(const uint32_t*)(sBlo + r0 * SROW + c0 + 8);
            }
            // 3 passes, 16 independent MMAs between same-acc dependents
#pragma unroll
            for (int mt = 0; mt < 2; mt++)
#pragma unroll
                for (int nt = 0; nt < 8; nt++) mma16816(acc[mt][nt], ah[mt], bh[nt]);
#pragma unroll
            for (int mt = 0; mt < 2; mt++)
#pragma unroll
                for (int nt = 0; nt < 8; nt++) mma16816(acc[mt][nt], ah[mt], bl[nt]);
#pragma unroll
            for (int mt = 0; mt < 2; mt++)
#pragma unroll
                for (int nt = 0; nt < 8; nt++) mma16816(acc[mt][nt], al[mt], bh[nt]);
        }
        __syncthreads();
    }

    // Epilogue
#pragma unroll
    for (int mt = 0; mt < 2; mt++) {
        int rbase = mrow0 + warp_m * 32 + mt * 16;
#pragma unroll
        for (int nt = 0; nt < 8; nt++) {
            int col = ncol0 + warp_n * 64 + nt * 8 + tig * 2;
            float b0 = 0.0f, b1 = 0.0f;
            if (EPI != 2) { b0 = bias[col]; b1 = bias[col + 1]; }
#pragma unroll
            for (int half = 0; half < 2; half++) {
                int r = rbase + g + half * 8;
                if (r >= M) continue;
                float v0 = acc[mt][nt][half * 2 + 0] + b0;
                float v1 = acc[mt][nt][half * 2 + 1] + b1;
                if (EPI != 2) { v0 = fmaxf(v0, 0.0f); v1 = fmaxf(v1, 0.0f); }
                if (EPI == 1) {
                    __nv_bfloat162 h, l;
                    split2(v0, v1, h, l);
                    size_t o = ((size_t)r * Ncols + col) >> 1;
                    Ohi[o] = h;
                    Olo[o] = l;
                } else {
                    *(float2*)(C + (size_t)r * Ncols + col) = make_float2(v0, v1);
                }
            }
        }
    }
}

// ===========================================================================
// fp32 GEMM (64x64) — tiny L4 (N=32)
// ===========================================================================
#define BM 64
#define BN 64
#define BK 16
__global__ __launch_bounds__(256)
void k_gemm(const float* __restrict__ A, const float* __restrict__ B,
            float* __restrict__ C, int M, int K, int N) {
    __shared__ float As[BK][BM + 4];
    __shared__ float Bs[BK][BN];
    const int block_row = blockIdx.y * BM;
    const int block_col = blockIdx.x * BN;
    const int tid = threadIdx.x;
    const int tr = (tid >> 4) << 2;
    const int tc = (tid & 15) << 2;
    float acc[4][4];
#pragma unroll
    for (int i = 0; i < 4; i++)
#pragma unroll
        for (int j = 0; j < 4; j++) acc[i][j] = 0.0f;
    for (int k0 = 0; k0 < K; k0 += BK) {
#pragma unroll
        for (int i = tid; i < BM * BK; i += 256) {
            int r = i >> 4, c = i & (BK - 1);
            int gr = block_row + r;
            As[c][r] = (gr < M) ? A[(size_t)gr * K + (k0 + c)] : 0.0f;
        }
#pragma unroll
        for (int i = tid; i < BK * BN; i += 256) {
            int r = i >> 6, c = i & (BN - 1);
            int gc = block_col + c;
            Bs[r][c] = (gc < N) ? B[(size_t)(k0 + r) * N + gc] : 0.0f;
        }
        __syncthreads();
#pragma unroll
        for (int k = 0; k < BK; ++k) {
            float a[4], b[4];
#pragma unroll
            for (int i = 0; i < 4; i++) a[i] = As[k][tr + i];
#pragma unroll
            for (int j = 0; j < 4; j++) b[j] = Bs[k][tc + j];
#pragma unroll
            for (int i = 0; i < 4; i++)
#pragma unroll
                for (int j = 0; j < 4; j++) acc[i][j] = fmaf(a[i], b[j], acc[i][j]);
        }
        __syncthreads();
    }
#pragma unroll
    for (int i = 0; i < 4; i++) {
        int gr = block_row + tr + i;
        if (gr >= M) continue;
#pragma unroll
        for (int j = 0; j < 4; j++) {
            int gc = block_col + tc + j;
            if (gc < N) C[(size_t)gr * N + gc] = acc[i][j];
        }
    }
}

// ===========================================================================
// Aggregations
// ===========================================================================
// fp32 -> fp32, block per node (used post-L3)
template <int H, bool RELU, bool HASBIAS>
__global__ __launch_bounds__(128)
void k_aggregate(const float4* __restrict__ lin,
                 const float*  __restrict__ bias,
                 float4* __restrict__ out) {
    constexpr int V = H / 4;
    constexpr int PER = (V + 127) / 128;
    const int node = blockIdx.x;
    const int tid = threadIdx.x;
    float dii = g_dinv[node];
    float w0 = dii * dii;

    float4 acc[PER];
#pragma unroll
    for (int p = 0; p < PER; p++) {
        int idx = tid + p * 128;
        if (idx < V) {
            float4 v = lin[(size_t)node * V + idx];
            acc[p] = make_float4(v.x * w0, v.y * w0, v.z * w0, v.w * w0);
        }
    }
    __shared__ int   s_col[128];
    __shared__ float s_w[128];
    const int beg = g_rowptr[node];
    const int end = g_rowptr[node + 1];
    for (int j0 = beg; j0 < end; j0 += 128) {
        int n = min(128, end - j0);
        __syncthreads();
        if (tid < n) { s_col[tid] = g_col[j0 + tid]; s_w[tid] = g_wt[j0 + tid]; }
        __syncthreads();
        for (int j = 0; j < n; j++) {
            int s = s_col[j];
            float w = s_w[j];
            const float4* row = lin + (size_t)s * V;
#pragma unroll
            for (int p = 0; p < PER; p++) {
                int idx = tid + p * 128;
                if (idx < V) {
                    float4 v = row[idx];
                    acc[p].x = fmaf(w, v.x, acc[p].x);
                    acc[p].y = fmaf(w, v.y, acc[p].y);
                    acc[p].z = fmaf(w, v.z, acc[p].z);
                    acc[p].w = fmaf(w, v.w, acc[p].w);
                }
            }
        }
    }
#pragma unroll
    for (int p = 0; p < PER; p++) {
        int idx = tid + p * 128;
        if (idx < V) {
            float4 r = acc[p];
            if (HASBIAS) {
                float4 b = reinterpret_cast<const float4*>(bias)[idx];
                r.x += b.x; r.y += b.y; r.z += b.z; r.w += b.w;
            }
            if (RELU) {
                r.x = fmaxf(r.x, 0.0f); r.y = fmaxf(r.y, 0.0f);
                r.z = fmaxf(r.z, 0.0f); r.w = fmaxf(r.w, 0.0f);
            }
            out[(size_t)node * V + idx] = r;
        }
    }
}

// fp32 -> bf16 hi/lo, block per node (pre-L2, H=512)
__global__ __launch_bounds__(128)
void k_agg512s(const float4* __restrict__ lin,
               __nv_bfloat162* __restrict__ ohi,
               __nv_bfloat162* __restrict__ olo) {
    const int node = blockIdx.x;
    const int tid = threadIdx.x;        // V = 128
    float dii = g_dinv[node];
    float w0 = dii * dii;
    float4 a = lin[(size_t)node * 128 + tid];
    a.x *= w0; a.y *= w0; a.z *= w0; a.w *= w0;

    __shared__ int   s_col[128];
    __shared__ float s_w[128];
    const int beg = g_rowptr[node];
    const int end = g_rowptr[node + 1];
    for (int j0 = beg; j0 < end; j0 += 128) {
        int n = min(128, end - j0);
        __syncthreads();
        if (tid < n) { s_col[tid] = g_col[j0 + tid]; s_w[tid] = g_wt[j0 + tid]; }
        __syncthreads();
        for (int j = 0; j < n; j++) {
            int s = s_col[j];
            float w = s_w[j];
            float4 v = lin[(size_t)s * 128 + tid];
            a.x = fmaf(w, v.x, a.x); a.y = fmaf(w, v.y, a.y);
            a.z = fmaf(w, v.z, a.z); a.w = fmaf(w, v.w, a.w);
        }
    }
    __nv_bfloat162 h01, h23, l01, l23;
    split2(a.x, a.y, h01, l01);
    split2(a.z, a.w, h23, l23);
    size_t o = (size_t)node * 256 + tid * 2;
    ohi[o] = h01; ohi[o + 1] = h23;
    olo[o] = l01; olo[o + 1] = l23;
}

// x [N,128] fp32 -> bf16 hi/lo with aggregation; warp per node, 8 nodes/block
__global__ __launch_bounds__(256)
void k_agg128s(const float4* __restrict__ lin,
               __nv_bfloat162* __restrict__ ohi,
               __nv_bfloat162* __restrict__ olo) {
    int node = blockIdx.x * 8 + threadIdx.y;
    if (node >= N_NODES) return;
    int lane = threadIdx.x;
    float dii = g_dinv[node];
    float w0 = dii * dii;
    float4 a = lin[(size_t)node * 32 + lane];
    a.x *= w0; a.y *= w0; a.z *= w0; a.w *= w0;
    int beg = g_rowptr[node], end = g_rowptr[node + 1];
    for (int j = beg; j < end; j++) {
        int s = g_col[j];
        float w = g_wt[j];
        float4 v = lin[(size_t)s * 32 + lane];
        a.x = fmaf(w, v.x, a.x); a.y = fmaf(w, v.y, a.y);
        a.z = fmaf(w, v.z, a.z); a.w = fmaf(w, v.w, a.w);
    }
    __nv_bfloat162 h01, h23, l01, l23;
    split2(a.x, a.y, h01, l01);
    split2(a.z, a.w, h23, l23);
    size_t o = (size_t)node * 64 + lane * 2;
    ohi[o] = h01; ohi[o + 1] = h23;
    olo[o] = l01; olo[o + 1] = l23;
}

// L4 final: aggregate (H=32) + bias + log_softmax; warp per node
__global__ __launch_bounds__(256)
void k_agg_softmax32(const float* __restrict__ lin,
                     const float* __restrict__ bias,
                     float* __restrict__ out) {
    int node = blockIdx.x * 8 + threadIdx.y;
    if (node >= N_NODES) return;
    int lane = threadIdx.x;
    float dii = g_dinv[node];
    float v = lin[(size_t)node * 32 + lane] * dii * dii;
    int beg = g_rowptr[node], end = g_rowptr[node + 1];
    for (int j = beg; j < end; j++) {
        int s = g_col[j];
        float w = g_wt[j];
        v = fmaf(w, lin[(size_t)s * 32 + lane], v);
    }
    v += bias[lane];
    float m = v;
#pragma unroll
    for (int o = 16; o > 0; o >>= 1)
        m = fmaxf(m, __shfl_xor_sync(0xFFFFFFFFu, m, o));
    float ex = expf(v - m);
    float s = ex;
#pragma unroll
    for (int o = 16; o > 0; o >>= 1)
        s += __shfl_xor_sync(0xFFFFFFFFu, s, o);
    out[(size_t)node * 32 + lane] = v - m - logf(s);
}

// ===========================================================================
// Launch
// ===========================================================================
static inline int cdiv(long long a, int b) { return (int)((a + b - 1) / b); }

extern "C" void kernel_launch(void* const* d_in, const int* in_sizes, int n_in,
                              void* d_out, int out_size) {
    const float* x  = (const float*)d_in[0];
    const void*  ei = d_in[1];
    const float* W1 = (const float*)d_in[2];
    const float* b1 = (const float*)d_in[3];
    const float* W2 = (const float*)d_in[4];
    const float* b2 = (const float*)d_in[5];
    const float* W3 = (const float*)d_in[6];
    const float* b3 = (const float*)d_in[7];
    const float* W4 = (const float*)d_in[8];
    const float* b4 = (const float*)d_in[9];
    float* out = (float*)d_out;

    const int E = in_sizes[1] / 2;

    float4 *buf0, *buf1;
    uint4 *Ahi, *Alo, *A2hi, *A2lo, *Bhi, *Blo;
    cudaGetSymbolAddress((void**)&buf0, g_buf0);
    cudaGetSymbolAddress((void**)&buf1, g_buf1);
    cudaGetSymbolAddress((void**)&Ahi, g_Ahi);
    cudaGetSymbolAddress((void**)&Alo, g_Alo);
    cudaGetSymbolAddress((void**)&A2hi, g_A2hi);
    cudaGetSymbolAddress((void**)&A2lo, g_A2lo);
    cudaGetSymbolAddress((void**)&Bhi, g_Bhi);
    cudaGetSymbolAddress((void**)&Blo, g_Blo);

    cudaFuncSetAttribute(k_gemm_mma<0>, cudaFuncAttributeMaxDynamicSharedMemorySize, GEMM_SMEM);
    cudaFuncSetAttribute(k_gemm_mma<1>, cudaFuncAttributeMaxDynamicSharedMemorySize, GEMM_SMEM);
    cudaFuncSetAttribute(k_gemm_mma<2>, cudaFuncAttributeMaxDynamicSharedMemorySize, GEMM_SMEM);

    const int MT = cdiv(N_NODES, 128);   // 79
    const __nv_bfloat16* BhiW = (const __nv_bfloat16*)Bhi;
    const __nv_bfloat16* BloW = (const __nv_bfloat16*)Blo;

    // --- CSR (4) + weights (1) ---
    k_zero_detect<<<cdiv(N_NODES, 256), 256>>>(ei);
    k_convert_count<<<cdiv(E, 256), 256>>>(ei, E);
    k_scan_dinv<<<1, 1024>>>();
    k_fill<<<cdiv(E, 256), 256>>>(E);
    k_splitT_all<<<1088, dim3(32, 8)>>>(W1, W2, W3,
                                        (__nv_bfloat16*)Bhi, (__nv_bfloat16*)Blo);

    // --- L1: agg+split (x) -> GEMM K=128 N=512 (bias+relu, fp32) -> buf1 ---
    k_agg128s<<<cdiv(N_NODES, 8), dim3(32, 8)>>>(
        (const float4*)x, (__nv_bfloat162*)Ahi, (__nv_bfloat162*)Alo);
    k_gemm_mma<0><<<dim3(H1_F / 128, MT), 256, GEMM_SMEM>>>(
        Ahi, Alo, BhiW + W1T_OFF, BloW + W1T_OFF, b1, (float*)buf1,
        nullptr, nullptr, N_NODES, IN_F, H1_F);

    // --- L2: agg+split (buf1) -> GEMM K=512 N=1024 (bias+relu, split out) ---
    k_agg512s<<<N_NODES, 128>>>(buf1, (__nv_bfloat162*)A2hi, (__nv_bfloat162*)A2lo);
    k_gemm_mma<1><<<dim3(H2_F / 128, MT), 256, GEMM_SMEM>>>(
        A2hi, A2lo, BhiW + W2T_OFF, BloW + W2T_OFF, b2, nullptr,
        (__nv_bfloat162*)Ahi, (__nv_bfloat162*)Alo, N_NODES, H1_F, H2_F);

    // --- L3: GEMM K=1024 N=512 (raw fp32) -> buf0 -> agg+bias+relu -> buf1 ---
    k_gemm_mma<2><<<dim3(H3_F / 128, MT), 256, GEMM_SMEM>>>(
        Ahi, Alo, BhiW + W3T_OFF, BloW + W3T_OFF, nullptr, (float*)buf0,
        nullptr, nullptr, N_NODES, H2_F, H3_F);
    k_aggregate<H3_F, true, true><<<N_NODES, 128>>>(buf0, b3, buf1);

    // --- L4: fp32 GEMM N=32 -> buf0 ; fused agg + bias + log_softmax ---
    {
        dim3 grid(1, cdiv(N_NODES, BM));
        k_gemm<<<grid, 256>>>((const float*)buf1, W4, (float*)buf0,
                              N_NODES, H3_F, OUT_F);
    }
    k_agg_softmax32<<<cdiv(N_NODES, 8), dim3(32, 8)>>>(
        (const float*)buf0, b4, out);
}

// round 8
// speedup vs baseline: 2.4877x; 1.2648x over previous
#include <cuda_runtime.h>
#include <cuda_fp16.h>
#include <math.h>
#include <stdint.h>

#define N_NODES 10000
#define E_EDGES 160000
#define IN_F    128
#define H1_F    512
#define H2_F    1024
#define H3_F    512
#define OUT_F   32

// Weight-transpose buffer offsets (fp16 elements)
#define W1T_OFF 0
#define W2T_OFF (IN_F * H1_F)
#define W3T_OFF (W2T_OFF + H1_F * H2_F)
#define WT_TOTAL (W3T_OFF + H2_F * H3_F)

// ===========================================================================
// Scratch (static device globals)
// ===========================================================================
__device__ int   g_is64;
__device__ int   g_src[E_EDGES];
__device__ int   g_dst[E_EDGES];
__device__ float g_dinv[N_NODES];
__device__ int   g_cnt[N_NODES];
__device__ int   g_cursor[N_NODES];
__device__ int   g_rowptr[N_NODES + 1];
__device__ int   g_col[E_EDGES];
__device__ float g_wt[E_EDGES];
__device__ float4 g_buf0[(size_t)N_NODES * H2_F / 4];
__device__ float4 g_buf1[(size_t)N_NODES * H2_F / 4];
__device__ uint4 g_A[(size_t)N_NODES * H2_F * 2 / 16];    // fp16 A (L3 / 1024)
__device__ uint4 g_A2[(size_t)N_NODES * H1_F * 2 / 16];   // fp16 A (L1/L2)
__device__ uint4 g_Bhi[(WT_TOTAL * 2 + 15) / 16];
__device__ uint4 g_Blo[(WT_TOTAL * 2 + 15) / 16];

// ===========================================================================
// helpers
// ===========================================================================
__device__ __forceinline__ uint32_t smem_to_u32(const void* p) {
    uint32_t a;
    asm("{ .reg .u64 t; cvta.to.shared.u64 t, %1; cvt.u32.u64 %0, t; }"
        : "=r"(a) : "l"(p));
    return a;
}
__device__ __forceinline__ void cp_async16(uint32_t s, const void* g) {
    asm volatile("cp.async.cg.shared.global [%0], [%1], 16;"
                 :: "r"(s), "l"(__cvta_generic_to_global(g)) : "memory");
}
__device__ __forceinline__ void cp_commit() {
    asm volatile("cp.async.commit_group;" ::: "memory");
}
template <int NN>
__device__ __forceinline__ void cp_wait() {
    asm volatile("cp.async.wait_group %0;" :: "n"(NN) : "memory");
}
__device__ __forceinline__ void mma16816(float* c, const uint32_t* a,
                                         const uint32_t* b) {
    asm volatile(
        "mma.sync.aligned.m16n8k16.row.col.f32.f16.f16.f32 "
        "{%0,%1,%2,%3}, {%4,%5,%6,%7}, {%8,%9}, {%0,%1,%2,%3};"
        : "+f"(c[0]), "+f"(c[1]), "+f"(c[2]), "+f"(c[3])
        : "r"(a[0]), "r"(a[1]), "r"(a[2]), "r"(a[3]), "r"(b[0]), "r"(b[1]));
}

// ===========================================================================
// CSR chain
// ===========================================================================
__global__ void k_zero_detect(const void* __restrict__ ei) {
    int i = blockIdx.x * blockDim.x + threadIdx.x;
    if (i < N_NODES) { g_cnt[i] = 0; g_cursor[i] = 0; }
    if (blockIdx.x == 0) {
        if (threadIdx.x == 0) g_is64 = 1;
        __syncthreads();
        if (threadIdx.x < 128) {
            const long long* p = (const long long*)ei;
            long long v = p[threadIdx.x];
            if (v < 0 || v >= N_NODES) atomicAnd(&g_is64, 0);
        }
    }
}
__global__ void k_convert_count(const void* __restrict__ ei, int E) {
    int e = blockIdx.x * blockDim.x + threadIdx.x;
    if (e >= E) return;
    int s, d;
    if (g_is64) {
        const long long* p = (const long long*)ei;
        s = (int)p[e]; d = (int)p[e + E];
    } else {
        const int* p = (const int*)ei;
        s = p[e]; d = p[e + E];
    }
    g_src[e] = s; g_dst[e] = d;
    atomicAdd(&g_cnt[d], 1);
}
__global__ __launch_bounds__(1024)
void k_scan_dinv() {
    __shared__ int wsum[32];
    __shared__ int s_off;
    const int tid = threadIdx.x;
    const int lane = tid & 31;
    const int wid = tid >> 5;
    if (tid == 0) s_off = 0;
    __syncthreads();
    for (int base = 0; base < N_NODES; base += 1024) {
        int i = base + tid;
        int v = (i < N_NODES) ? g_cnt[i] : 0;
        if (i < N_NODES) g_dinv[i] = rsqrtf((float)v + 1.0f);
        int x = v;
#pragma unroll
        for (int o = 1; o < 32; o <<= 1) {
            int t = __shfl_up_sync(0xFFFFFFFFu, x, o);
            if (lane >= o) x += t;
        }
        if (lane == 31) wsum[wid] = x;
        __syncthreads();
        if (wid == 0) {
            int w = wsum[lane];
#pragma unroll
            for (int o = 1; o < 32; o <<= 1) {
                int t = __shfl_up_sync(0xFFFFFFFFu, w, o);
                if (lane >= o) w += t;
            }
            wsum[lane] = w;
        }
        __syncthreads();
        int incl = x + ((wid > 0) ? wsum[wid - 1] : 0);
        int off = s_off;
        if (i < N_NODES) g_rowptr[i + 1] = off + incl;
        __syncthreads();
        if (tid == 1023) s_off = off + incl;
        __syncthreads();
    }
    if (tid == 0) g_rowptr[0] = 0;
}
__global__ void k_fill(int E) {
    int e = blockIdx.x * blockDim.x + threadIdx.x;
    if (e >= E) return;
    int s = g_src[e];
    int d = g_dst[e];
    float w = g_dinv[s] * g_dinv[d];
    int pos = g_rowptr[d] + atomicAdd(&g_cursor[d], 1);
    g_col[pos] = s;
    g_wt[pos]  = w;
}

// ===========================================================================
// All-weights transpose + split: W[K,N] fp32 -> [N,K] fp16 hi/lo
// ===========================================================================
__global__ __launch_bounds__(256)
void k_splitT_all(const float* __restrict__ W1, const float* __restrict__ W2,
                  const float* __restrict__ W3,
                  __half* __restrict__ hi, __half* __restrict__ lo) {
    const float* W; int K, N; size_t off;
    int b = blockIdx.x;
    if (b < 64)       { W = W1; K = IN_F; N = H1_F; off = W1T_OFF; }
    else if (b < 576) { b -= 64;  W = W2; K = H1_F; N = H2_F; off = W2T_OFF; }
    else              { b -= 576; W = W3; K = H2_F; N = H3_F; off = W3T_OFF; }
    int KT = K / 32;
    int k0 = (b % KT) * 32, n0 = (b / KT) * 32;

    __shared__ float t[32][33];
    int tx = threadIdx.x, ty = threadIdx.y;
#pragma unroll
    for (int j = 0; j < 4; j++)
        t[ty + j * 8][tx] = W[(size_t)(k0 + ty + j * 8) * N + (n0 + tx)];
    __syncthreads();
#pragma unroll
    for (int j = 0; j < 4; j++) {
        float v = t[tx][ty + j * 8];
        int n = n0 + ty + j * 8;
        int k = k0 + tx;
        __half h = __float2half_rn(v);
        __half l = __float2half_rn(v - __half2float(h));
        hi[off + (size_t)n * K + k] = h;
        lo[off + (size_t)n * K + k] = l;
    }
}

// ===========================================================================
// fp16 2-pass GEMM: C[M,N] = A[M,K] @ B[K,N]
//   A fp16 [M,K]; B fp16 hi/lo [N,K]. Passes: A*Bhi + A*Blo. fp32 acc.
//   CTA 128x128, 8 warps 4mx2n, 2-stage cp.async pipeline.
// EPI: 0 = bias+relu fp32, 1 = bias+relu -> fp16, 2 = raw fp32
// ===========================================================================
#define KC 32
#define SROW 40                      // fp16 row stride (80 B)
#define TILE_B (128 * SROW * 2)      // 10240 B
#define STAGE_B (3 * TILE_B)         // 30720 B (A, Bhi, Blo)
#define GEMM_SMEM (2 * STAGE_B)      // 61440 B

template <int EPI>
__global__ __launch_bounds__(256)
void k_gemm_mma(const uint4* __restrict__ A,
                const __half* __restrict__ Bhi, const __half* __restrict__ Blo,
                const float* __restrict__ bias, float* __restrict__ C,
                __half2* __restrict__ Oh,
                int M, int K, int Ncols) {
    extern __shared__ char sm[];
    const uint32_t smb = smem_to_u32(sm);
    const int tid = threadIdx.x;
    const int lane = tid & 31;
    const int wid = tid >> 5;
    const int warp_m = wid & 3;
    const int warp_n = wid >> 2;
    const int g = lane >> 2;
    const int tig = lane & 3;
    const int mrow0 = blockIdx.y * 128;
    const int ncol0 = blockIdx.x * 128;
    const int KU = K >> 3;
    const int nChunks = K / KC;

    float acc[2][8][4];
#pragma unroll
    for (int i = 0; i < 2; i++)
#pragma unroll
        for (int j = 0; j < 8; j++)
#pragma unroll
            for (int q = 0; q < 4; q++) acc[i][j][q] = 0.0f;

    auto load_chunk = [&](int it, int st) {
        const int ku0 = it * (KC / 8);
        const uint32_t sb = smb + st * STAGE_B;
#pragma unroll
        for (int q = tid; q < 512; q += 256) {
            int row = q >> 2;
            int cb = q & 3;
            uint32_t so = (uint32_t)(row * 80 + cb * 16);
            int gm = mrow0 + row;
            if (gm < M) {
                cp_async16(sb + so, A + (size_t)gm * KU + ku0 + cb);
            } else {
                *(uint4*)(sm + st * STAGE_B + so) = make_uint4(0, 0, 0, 0);
            }
            size_t bb = (size_t)(ncol0 + row) * K + it * KC + cb * 8;
            cp_async16(sb + TILE_B + so, Bhi + bb);
            cp_async16(sb + 2 * TILE_B + so, Blo + bb);
        }
        cp_commit();
    };

    load_chunk(0, 0);
    for (int it = 0; it < nChunks; it++) {
        const int cur = it & 1;
        if (it + 1 < nChunks) {
            load_chunk(it + 1, cur ^ 1);
            cp_wait<1>();
        } else {
            cp_wait<0>();
        }
        __syncthreads();

        const __half* sA   = (const __half*)(sm + cur * STAGE_B);
        const __half* sBhi = (const __half*)(sm + cur * STAGE_B + TILE_B);
        const __half* sBlo = (const __half*)(sm + cur * STAGE_B + 2 * TILE_B);

#pragma unroll
        for (int ks = 0; ks < KC / 16; ks++) {
            const int k0 = ks * 16;
            uint32_t ah[2][4];
#pragma unroll
            for (int mt = 0; mt < 2; mt++) {
                int r0 = warp_m * 32 + mt * 16 + g;
                int c0 = k0 + tig * 2;
                ah[mt][0] = *(const uint32_t*)(sA + r0 * SROW + c0);
                ah[mt][1] = *(const uint32_t*)(sA + (r0 + 8) * SROW + c0);
                ah[mt][2] = *(const uint32_t*)(sA + r0 * SROW + c0 + 8);
                ah[mt][3] = *(const uint32_t*)(sA + (r0 + 8) * SROW + c0 + 8);
            }
            uint32_t bh[8][2], bl[8][2];
#pragma unroll
            for (int nt = 0; nt < 8; nt++) {
                int r0 = warp_n * 64 + nt * 8 + g;
                int c0 = k0 + tig * 2;
                bh[nt][0] = *(const uint32_t*)(sBhi + r0 * SROW + c0);
                bh[nt][1] = *(const uint32_t*)(sBhi + r0 * SROW + c0 + 8);
                bl[nt][0] = *(const uint32_t*)(sBlo + r0 * SROW + c0);
                bl[nt][1] = *(const uint32_t*)(sBlo + r0 * SROW + c0 + 8);
            }
#pragma unroll
            for (int mt = 0; mt < 2; mt++)
#pragma unroll
                for (int nt = 0; nt < 8; nt++) mma16816(acc[mt][nt], ah[mt], bh[nt]);
#pragma unroll
            for (int mt = 0; mt < 2; mt++)
#pragma unroll
                for (int nt = 0; nt < 8; nt++) mma16816(acc[mt][nt], ah[mt], bl[nt]);
        }
        __syncthreads();
    }

    // Epilogue
#pragma unroll
    for (int mt = 0; mt < 2; mt++) {
        int rbase = mrow0 + warp_m * 32 + mt * 16;
#pragma unroll
        for (int nt = 0; nt < 8; nt++) {
            int col = ncol0 + warp_n * 64 + nt * 8 + tig * 2;
            float b0 = 0.0f, b1 = 0.0f;
            if (EPI != 2) { b0 = bias[col]; b1 = bias[col + 1]; }
#pragma unroll
            for (int half = 0; half < 2; half++) {
                int r = rbase + g + half * 8;
                if (r >= M) continue;
                float v0 = acc[mt][nt][half * 2 + 0] + b0;
                float v1 = acc[mt][nt][half * 2 + 1] + b1;
                if (EPI != 2) { v0 = fmaxf(v0, 0.0f); v1 = fmaxf(v1, 0.0f); }
                if (EPI == 1) {
                    Oh[((size_t)r * Ncols + col) >> 1] = __floats2half2_rn(v0, v1);
                } else {
                    *(float2*)(C + (size_t)r * Ncols + col) = make_float2(v0, v1);
                }
            }
        }
    }
}

// ===========================================================================
// fp32 GEMM (64x64) — tiny L4 (N=32)
// ===========================================================================
#define BM 64
#define BN 64
#define BK 16
__global__ __launch_bounds__(256)
void k_gemm(const float* __restrict__ A, const float* __restrict__ B,
            float* __restrict__ C, int M, int K, int N) {
    __shared__ float As[BK][BM + 4];
    __shared__ float Bs[BK][BN];
    const int block_row = blockIdx.y * BM;
    const int block_col = blockIdx.x * BN;
    const int tid = threadIdx.x;
    const int tr = (tid >> 4) << 2;
    const int tc = (tid & 15) << 2;
    float acc[4][4];
#pragma unroll
    for (int i = 0; i < 4; i++)
#pragma unroll
        for (int j = 0; j < 4; j++) acc[i][j] = 0.0f;
    for (int k0 = 0; k0 < K; k0 += BK) {
#pragma unroll
        for (int i = tid; i < BM * BK; i += 256) {
            int r = i >> 4, c = i & (BK - 1);
            int gr = block_row + r;
            As[c][r] = (gr < M) ? A[(size_t)gr * K + (k0 + c)] : 0.0f;
        }
#pragma unroll
        for (int i = tid; i < BK * BN; i += 256) {
            int r = i >> 6, c = i & (BN - 1);
            int gc = block_col + c;
            Bs[r][c] = (gc < N) ? B[(size_t)(k0 + r) * N + gc] : 0.0f;
        }
        __syncthreads();
#pragma unroll
        for (int k = 0; k < BK; ++k) {
            float a[4], b[4];
#pragma unroll
            for (int i = 0; i < 4; i++) a[i] = As[k][tr + i];
#pragma unroll
            for (int j = 0; j < 4; j++) b[j] = Bs[k][tc + j];
#pragma unroll
            for (int i = 0; i < 4; i++)
#pragma unroll
                for (int j = 0; j < 4; j++) acc[i][j] = fmaf(a[i], b[j], acc[i][j]);
        }
        __syncthreads();
    }
#pragma unroll
    for (int i = 0; i < 4; i++) {
        int gr = block_row + tr + i;
        if (gr >= M) continue;
#pragma unroll
        for (int j = 0; j < 4; j++) {
            int gc = block_col + tc + j;
            if (gc < N) C[(size_t)gr * N + gc] = acc[i][j];
        }
    }
}

// ===========================================================================
// Aggregations
// ===========================================================================
// fp32 -> fp32, block per node (post-L3)
template <int H, bool RELU, bool HASBIAS>
__global__ __launch_bounds__(128)
void k_aggregate(const float4* __restrict__ lin,
                 const float*  __restrict__ bias,
                 float4* __restrict__ out) {
    constexpr int V = H / 4;
    constexpr int PER = (V + 127) / 128;
    const int node = blockIdx.x;
    const int tid = threadIdx.x;
    float dii = g_dinv[node];
    float w0 = dii * dii;

    float4 acc[PER];
#pragma unroll
    for (int p = 0; p < PER; p++) {
        int idx = tid + p * 128;
        if (idx < V) {
            float4 v = lin[(size_t)node * V + idx];
            acc[p] = make_float4(v.x * w0, v.y * w0, v.z * w0, v.w * w0);
        }
    }
    __shared__ int   s_col[128];
    __shared__ float s_w[128];
    const int beg = g_rowptr[node];
    const int end = g_rowptr[node + 1];
    for (int j0 = beg; j0 < end; j0 += 128) {
        int n = min(128, end - j0);
        __syncthreads();
        if (tid < n) { s_col[tid] = g_col[j0 + tid]; s_w[tid] = g_wt[j0 + tid]; }
        __syncthreads();
        for (int j = 0; j < n; j++) {
            int s = s_col[j];
            float w = s_w[j];
            const float4* row = lin + (size_t)s * V;
#pragma unroll
            for (int p = 0; p < PER; p++) {
                int idx = tid + p * 128;
                if (idx < V) {
                    float4 v = row[idx];
                    acc[p].x = fmaf(w, v.x, acc[p].x);
                    acc[p].y = fmaf(w, v.y, acc[p].y);
                    acc[p].z = fmaf(w, v.z, acc[p].z);
                    acc[p].w = fmaf(w, v.w, acc[p].w);
                }
            }
        }
    }
#pragma unroll
    for (int p = 0; p < PER; p++) {
        int idx = tid + p * 128;
        if (idx < V) {
            float4 r = acc[p];
            if (HASBIAS) {
                float4 b = reinterpret_cast<const float4*>(bias)[idx];
                r.x += b.x; r.y += b.y; r.z += b.z; r.w += b.w;
            }
            if (RELU) {
                r.x = fmaxf(r.x, 0.0f); r.y = fmaxf(r.y, 0.0f);
                r.z = fmaxf(r.z, 0.0f); r.w = fmaxf(r.w, 0.0f);
            }
            out[(size_t)node * V + idx] = r;
        }
    }
}

// fp32 -> fp16, block per node (pre-L2, H=512)
__global__ __launch_bounds__(128)
void k_agg512h(const float4* __restrict__ lin, __half2* __restrict__ oh) {
    const int node = blockIdx.x;
    const int tid = threadIdx.x;
    float dii = g_dinv[node];
    float w0 = dii * dii;
    float4 a = lin[(size_t)node * 128 + tid];
    a.x *= w0; a.y *= w0; a.z *= w0; a.w *= w0;

    __shared__ int   s_col[128];
    __shared__ float s_w[128];
    const int beg = g_rowptr[node];
    const int end = g_rowptr[node + 1];
    for (int j0 = beg; j0 < end; j0 += 128) {
        int n = min(128, end - j0);
        __syncthreads();
        if (tid < n) { s_col[tid] = g_col[j0 + tid]; s_w[tid] = g_wt[j0 + tid]; }
        __syncthreads();
        for (int j = 0; j < n; j++) {
            int s = s_col[j];
            float w = s_w[j];
            float4 v = lin[(size_t)s * 128 + tid];
            a.x = fmaf(w, v.x, a.x); a.y = fmaf(w, v.y, a.y);
            a.z = fmaf(w, v.z, a.z); a.w = fmaf(w, v.w, a.w);
        }
    }
    size_t o = (size_t)node * 256 + tid * 2;
    oh[o]     = __floats2half2_rn(a.x, a.y);
    oh[o + 1] = __floats2half2_rn(a.z, a.w);
}

// x [N,128] fp32 -> fp16 with aggregation; warp per node, 8 nodes/block
__global__ __launch_bounds__(256)
void k_agg128h(const float4* __restrict__ lin, __half2* __restrict__ oh) {
    int node = blockIdx.x * 8 + threadIdx.y;
    if (node >= N_NODES) return;
    int lane = threadIdx.x;
    float dii = g_dinv[node];
    float w0 = dii * dii;
    float4 a = lin[(size_t)node * 32 + lane];
    a.x *= w0; a.y *= w0; a.z *= w0; a.w *= w0;
    int beg = g_rowptr[node], end = g_rowptr[node + 1];
    for (int j = beg; j < end; j++) {
        int s = g_col[j];
        float w = g_wt[j];
        float4 v = lin[(size_t)s * 32 + lane];
        a.x = fmaf(w, v.x, a.x); a.y = fmaf(w, v.y, a.y);
        a.z = fmaf(w, v.z, a.z); a.w = fmaf(w, v.w, a.w);
    }
    size_t o = (size_t)node * 64 + lane * 2;
    oh[o]     = __floats2half2_rn(a.x, a.y);
    oh[o + 1] = __floats2half2_rn(a.z, a.w);
}

// L4 final: aggregate (H=32) + bias + log_softmax; warp per node
__global__ __launch_bounds__(256)
void k_agg_softmax32(const float* __restrict__ lin,
                     const float* __restrict__ bias,
                     float* __restrict__ out) {
    int node = blockIdx.x * 8 + threadIdx.y;
    if (node >= N_NODES) return;
    int lane = threadIdx.x;
    float dii = g_dinv[node];
    float v = lin[(size_t)node * 32 + lane] * dii * dii;
    int beg = g_rowptr[node], end = g_rowptr[node + 1];
    for (int j = beg; j < end; j++) {
        int s = g_col[j];
        float w = g_wt[j];
        v = fmaf(w, lin[(size_t)s * 32 + lane], v);
    }
    v += bias[lane];
    float m = v;
#pragma unroll
    for (int o = 16; o > 0; o >>= 1)
        m = fmaxf(m, __shfl_xor_sync(0xFFFFFFFFu, m, o));
    float ex = expf(v - m);
    float s = ex;
#pragma unroll
    for (int o = 16; o > 0; o >>= 1)
        s += __shfl_xor_sync(0xFFFFFFFFu, s, o);
    out[(size_t)node * 32 + lane] = v - m - logf(s);
}

// ===========================================================================
// Launch
// ===========================================================================
static inline int cdiv(long long a, int b) { return (int)((a + b - 1) / b); }

extern "C" void kernel_launch(void* const* d_in, const int* in_sizes, int n_in,
                              void* d_out, int out_size) {
    const float* x  = (const float*)d_in[0];
    const void*  ei = d_in[1];
    const float* W1 = (const float*)d_in[2];
    const float* b1 = (const float*)d_in[3];
    const float* W2 = (const float*)d_in[4];
    const float* b2 = (const float*)d_in[5];
    const float* W3 = (const float*)d_in[6];
    const float* b3 = (const float*)d_in[7];
    const float* W4 = (const float*)d_in[8];
    const float* b4 = (const float*)d_in[9];
    float* out = (float*)d_out;

    const int E = in_sizes[1] / 2;

    float4 *buf0, *buf1;
    uint4 *A, *A2, *Bhi, *Blo;
    cudaGetSymbolAddress((void**)&buf0, g_buf0);
    cudaGetSymbolAddress((void**)&buf1, g_buf1);
    cudaGetSymbolAddress((void**)&A, g_A);
    cudaGetSymbolAddress((void**)&A2, g_A2);
    cudaGetSymbolAddress((void**)&Bhi, g_Bhi);
    cudaGetSymbolAddress((void**)&Blo, g_Blo);

    cudaFuncSetAttribute(k_gemm_mma<0>, cudaFuncAttributeMaxDynamicSharedMemorySize, GEMM_SMEM);
    cudaFuncSetAttribute(k_gemm_mma<1>, cudaFuncAttributeMaxDynamicSharedMemorySize, GEMM_SMEM);
    cudaFuncSetAttribute(k_gemm_mma<2>, cudaFuncAttributeMaxDynamicSharedMemorySize, GEMM_SMEM);

    const int MT = cdiv(N_NODES, 128);
    const __half* BhiW = (const __half*)Bhi;
    const __half* BloW = (const __half*)Blo;

    // --- CSR + weights ---
    k_zero_detect<<<cdiv(N_NODES, 256), 256>>>(ei);
    k_convert_count<<<cdiv(E, 256), 256>>>(ei, E);
    k_scan_dinv<<<1, 1024>>>();
    k_fill<<<cdiv(E, 256), 256>>>(E);
    k_splitT_all<<<1088, dim3(32, 8)>>>(W1, W2, W3, (__half*)Bhi, (__half*)Blo);

    // --- L1: agg->fp16 (x) -> GEMM K=128 N=512 (bias+relu fp32) -> buf1 ---
    k_agg128h<<<cdiv(N_NODES, 8), dim3(32, 8)>>>((const float4*)x, (__half2*)A2);
    k_gemm_mma<0><<<dim3(H1_F / 128, MT), 256, GEMM_SMEM>>>(
        A2, BhiW + W1T_OFF, BloW + W1T_OFF, b1, (float*)buf1,
        nullptr, N_NODES, IN_F, H1_F);

    // --- L2: agg->fp16 (buf1) -> GEMM K=512 N=1024 (bias+relu -> fp16 A) ---
    k_agg512h<<<N_NODES, 128>>>(buf1, (__half2*)A2);
    k_gemm_mma<1><<<dim3(H2_F / 128, MT), 256, GEMM_SMEM>>>(
        A2, BhiW + W2T_OFF, BloW + W2T_OFF, b2, nullptr,
        (__half2*)A, N_NODES, H1_F, H2_F);

    // --- L3: GEMM K=1024 N=512 (raw fp32) -> buf0 -> agg+bias+relu -> buf1 ---
    k_gemm_mma<2><<<dim3(H3_F / 128, MT), 256, GEMM_SMEM>>>(
        A, BhiW + W3T_OFF, BloW + W3T_OFF, nullptr, (float*)buf0,
        nullptr, N_NODES, H2_F, H3_F);
    k_aggregate<H3_F, true, true><<<N_NODES, 128>>>(buf0, b3, buf1);

    // --- L4: fp32 GEMM N=32 -> buf0 ; fused agg + bias + log_softmax ---
    {
        dim3 grid(1, cdiv(N_NODES, BM));
        k_gemm<<<grid, 256>>>((const float*)buf1, W4, (float*)buf0,
                              N_NODES, H3_F, OUT_F);
    }
    k_agg_softmax32<<<cdiv(N_NODES, 8), dim3(32, 8)>>>(
        (const float*)buf0, b4, out);
}

// round 9
// speedup vs baseline: 3.5679x; 1.4342x over previous
#include <cuda_runtime.h>
#include <cuda_fp16.h>
#include <math.h>
#include <stdint.h>

#define N_NODES 10000
#define E_EDGES 160000
#define IN_F    128
#define H1_F    512
#define H2_F    1024
#define H3_F    512
#define OUT_F   32

// Weight-transpose buffer offsets (fp16 elements)
#define W1T_OFF 0
#define W2T_OFF (IN_F * H1_F)
#define W3T_OFF (W2T_OFF + H1_F * H2_F)
#define WT_TOTAL (W3T_OFF + H2_F * H3_F)

// ===========================================================================
// Scratch (static device globals)
// ===========================================================================
__device__ int   g_is64;
__device__ int   g_src[E_EDGES];
__device__ int   g_dst[E_EDGES];
__device__ float g_dinv[N_NODES];
__device__ int   g_cnt[N_NODES];
__device__ int   g_cursor[N_NODES];
__device__ int   g_rowptr[N_NODES + 1];
__device__ int   g_col[E_EDGES];
__device__ float g_wt[E_EDGES];
__device__ float4 g_buf0[(size_t)N_NODES * H1_F / 4];   // fp32 scratch
__device__ float4 g_buf1[(size_t)N_NODES * H1_F / 4];   // fp32 scratch
__device__ uint4 g_A[(size_t)N_NODES * H2_F * 2 / 16];  // fp16 activations A
__device__ uint4 g_A2[(size_t)N_NODES * H1_F * 2 / 16]; // fp16 activations B
__device__ uint4 g_Bh[(WT_TOTAL * 2 + 15) / 16];        // fp16 weights (T)

// ===========================================================================
// helpers
// ===========================================================================
__device__ __forceinline__ uint32_t smem_to_u32(const void* p) {
    uint32_t a;
    asm("{ .reg .u64 t; cvta.to.shared.u64 t, %1; cvt.u32.u64 %0, t; }"
        : "=r"(a) : "l"(p));
    return a;
}
__device__ __forceinline__ void cp_async16(uint32_t s, const void* g) {
    asm volatile("cp.async.cg.shared.global [%0], [%1], 16;"
                 :: "r"(s), "l"(__cvta_generic_to_global(g)) : "memory");
}
__device__ __forceinline__ void cp_commit() {
    asm volatile("cp.async.commit_group;" ::: "memory");
}
template <int NN>
__device__ __forceinline__ void cp_wait() {
    asm volatile("cp.async.wait_group %0;" :: "n"(NN) : "memory");
}
__device__ __forceinline__ void mma16816(float* c, const uint32_t* a,
                                         const uint32_t* b) {
    asm volatile(
        "mma.sync.aligned.m16n8k16.row.col.f32.f16.f16.f32 "
        "{%0,%1,%2,%3}, {%4,%5,%6,%7}, {%8,%9}, {%0,%1,%2,%3};"
        : "+f"(c[0]), "+f"(c[1]), "+f"(c[2]), "+f"(c[3])
        : "r"(a[0]), "r"(a[1]), "r"(a[2]), "r"(a[3]), "r"(b[0]), "r"(b[1]));
}

// ===========================================================================
// CSR chain
// ===========================================================================
__global__ void k_zero_detect(const void* __restrict__ ei) {
    int i = blockIdx.x * blockDim.x + threadIdx.x;
    if (i < N_NODES) { g_cnt[i] = 0; g_cursor[i] = 0; }
    if (blockIdx.x == 0) {
        if (threadIdx.x == 0) g_is64 = 1;
        __syncthreads();
        if (threadIdx.x < 128) {
            const long long* p = (const long long*)ei;
            long long v = p[threadIdx.x];
            if (v < 0 || v >= N_NODES) atomicAnd(&g_is64, 0);
        }
    }
}
__global__ void k_convert_count(const void* __restrict__ ei, int E) {
    int e = blockIdx.x * blockDim.x + threadIdx.x;
    if (e >= E) return;
    int s, d;
    if (g_is64) {
        const long long* p = (const long long*)ei;
        s = (int)p[e]; d = (int)p[e + E];
    } else {
        const int* p = (const int*)ei;
        s = p[e]; d = p[e + E];
    }
    g_src[e] = s; g_dst[e] = d;
    atomicAdd(&g_cnt[d], 1);
}
__global__ __launch_bounds__(1024)
void k_scan_dinv() {
    __shared__ int wsum[32];
    __shared__ int s_off;
    const int tid = threadIdx.x;
    const int lane = tid & 31;
    const int wid = tid >> 5;
    if (tid == 0) s_off = 0;
    __syncthreads();
    for (int base = 0; base < N_NODES; base += 1024) {
        int i = base + tid;
        int v = (i < N_NODES) ? g_cnt[i] : 0;
        if (i < N_NODES) g_dinv[i] = rsqrtf((float)v + 1.0f);
        int x = v;
#pragma unroll
        for (int o = 1; o < 32; o <<= 1) {
            int t = __shfl_up_sync(0xFFFFFFFFu, x, o);
            if (lane >= o) x += t;
        }
        if (lane == 31) wsum[wid] = x;
        __syncthreads();
        if (wid == 0) {
            int w = wsum[lane];
#pragma unroll
            for (int o = 1; o < 32; o <<= 1) {
                int t = __shfl_up_sync(0xFFFFFFFFu, w, o);
                if (lane >= o) w += t;
            }
            wsum[lane] = w;
        }
        __syncthreads();
        int incl = x + ((wid > 0) ? wsum[wid - 1] : 0);
        int off = s_off;
        if (i < N_NODES) g_rowptr[i + 1] = off + incl;
        __syncthreads();
        if (tid == 1023) s_off = off + incl;
        __syncthreads();
    }
    if (tid == 0) g_rowptr[0] = 0;
}
__global__ void k_fill(int E) {
    int e = blockIdx.x * blockDim.x + threadIdx.x;
    if (e >= E) return;
    int s = g_src[e];
    int d = g_dst[e];
    float w = g_dinv[s] * g_dinv[d];
    int pos = g_rowptr[d] + atomicAdd(&g_cursor[d], 1);
    g_col[pos] = s;
    g_wt[pos]  = w;
}

// ===========================================================================
// All-weights transpose + fp16 convert: W[K,N] fp32 -> [N,K] fp16
// ===========================================================================
__global__ __launch_bounds__(256)
void k_transT_all(const float* __restrict__ W1, const float* __restrict__ W2,
                  const float* __restrict__ W3, __half* __restrict__ hi) {
    const float* W; int K, N; size_t off;
    int b = blockIdx.x;
    if (b < 64)       { W = W1; K = IN_F; N = H1_F; off = W1T_OFF; }
    else if (b < 576) { b -= 64;  W = W2; K = H1_F; N = H2_F; off = W2T_OFF; }
    else              { b -= 576; W = W3; K = H2_F; N = H3_F; off = W3T_OFF; }
    int KT = K / 32;
    int k0 = (b % KT) * 32, n0 = (b / KT) * 32;

    __shared__ float t[32][33];
    int tx = threadIdx.x, ty = threadIdx.y;
#pragma unroll
    for (int j = 0; j < 4; j++)
        t[ty + j * 8][tx] = W[(size_t)(k0 + ty + j * 8) * N + (n0 + tx)];
    __syncthreads();
#pragma unroll
    for (int j = 0; j < 4; j++) {
        float v = t[tx][ty + j * 8];
        int n = n0 + ty + j * 8;
        int k = k0 + tx;
        hi[off + (size_t)n * K + k] = __float2half_rn(v);
    }
}

// ===========================================================================
// fp16 1-pass GEMM: C[M,N] = A[M,K] @ B[K,N]
//   A fp16 [M,K]; B fp16 [N,K] pre-transposed. fp32 accumulate.
//   CTA 128x128, 8 warps 4mx2n, 2-stage cp.async pipeline.
// EPI: 0 = bias+relu fp32 C, 1 = bias+relu fp16 Oh, 2 = raw fp16 Oh
// ===========================================================================
#define KC 32
#define SROW 40                      // fp16 row stride (80 B)
#define TILE_B (128 * SROW * 2)      // 10240 B
#define STAGE_B (2 * TILE_B)         // 20480 B (A, B)
#define GEMM_SMEM (2 * STAGE_B)      // 40960 B

template <int EPI>
__global__ __launch_bounds__(256)
void k_gemm_mma(const uint4* __restrict__ A, const __half* __restrict__ B,
                const float* __restrict__ bias, float* __restrict__ C,
                __half2* __restrict__ Oh,
                int M, int K, int Ncols) {
    extern __shared__ char sm[];
    const uint32_t smb = smem_to_u32(sm);
    const int tid = threadIdx.x;
    const int lane = tid & 31;
    const int wid = tid >> 5;
    const int warp_m = wid & 3;
    const int warp_n = wid >> 2;
    const int g = lane >> 2;
    const int tig = lane & 3;
    const int mrow0 = blockIdx.y * 128;
    const int ncol0 = blockIdx.x * 128;
    const int KU = K >> 3;
    const int nChunks = K / KC;

    float acc[2][8][4];
#pragma unroll
    for (int i = 0; i < 2; i++)
#pragma unroll
        for (int j = 0; j < 8; j++)
#pragma unroll
            for (int q = 0; q < 4; q++) acc[i][j][q] = 0.0f;

    auto load_chunk = [&](int it, int st) {
        const int ku0 = it * (KC / 8);
        const uint32_t sb = smb + st * STAGE_B;
#pragma unroll
        for (int q = tid; q < 512; q += 256) {
            int row = q >> 2;
            int cb = q & 3;
            uint32_t so = (uint32_t)(row * 80 + cb * 16);
            int gm = mrow0 + row;
            if (gm < M) {
                cp_async16(sb + so, A + (size_t)gm * KU + ku0 + cb);
            } else {
                *(uint4*)(sm + st * STAGE_B + so) = make_uint4(0, 0, 0, 0);
            }
            size_t bb = (size_t)(ncol0 + row) * K + it * KC + cb * 8;
            cp_async16(sb + TILE_B + so, B + bb);
        }
        cp_commit();
    };

    load_chunk(0, 0);
    for (int it = 0; it < nChunks; it++) {
        const int cur = it & 1;
        if (it + 1 < nChunks) {
            load_chunk(it + 1, cur ^ 1);
            cp_wait<1>();
        } else {
            cp_wait<0>();
        }
        __syncthreads();

        const __half* sA = (const __half*)(sm + cur * STAGE_B);
        const __half* sB = (const __half*)(sm + cur * STAGE_B + TILE_B);

#pragma unroll
        for (int ks = 0; ks < KC / 16; ks++) {
            const int k0 = ks * 16;
            uint32_t ah[2][4];
#pragma unroll
            for (int mt = 0; mt < 2; mt++) {
                int r0 = warp_m * 32 + mt * 16 + g;
                int c0 = k0 + tig * 2;
                ah[mt][0] = *(const uint32_t*)(sA + r0 * SROW + c0);
                ah[mt][1] = *(const uint32_t*)(sA + (r0 + 8) * SROW + c0);
                ah[mt][2] = *(const uint32_t*)(sA + r0 * SROW + c0 + 8);
                ah[mt][3] = *(const uint32_t*)(sA + (r0 + 8) * SROW + c0 + 8);
            }
            uint32_t bh[8][2];
#pragma unroll
            for (int nt = 0; nt < 8; nt++) {
                int r0 = warp_n * 64 + nt * 8 + g;
                int c0 = k0 + tig * 2;
                bh[nt][0] = *(const uint32_t*)(sB + r0 * SROW + c0);
                bh[nt][1] = *(const uint32_t*)(sB + r0 * SROW + c0 + 8);
            }
#pragma unroll
            for (int mt = 0; mt < 2; mt++)
#pragma unroll
                for (int nt = 0; nt < 8; nt++) mma16816(acc[mt][nt], ah[mt], bh[nt]);
        }
        __syncthreads();
    }

    // Epilogue
#pragma unroll
    for (int mt = 0; mt < 2; mt++) {
        int rbase = mrow0 + warp_m * 32 + mt * 16;
#pragma unroll
        for (int nt = 0; nt < 8; nt++) {
            int col = ncol0 + warp_n * 64 + nt * 8 + tig * 2;
            float b0 = 0.0f, b1 = 0.0f;
            if (EPI != 2) { b0 = bias[col]; b1 = bias[col + 1]; }
#pragma unroll
            for (int half = 0; half < 2; half++) {
                int r = rbase + g + half * 8;
                if (r >= M) continue;
                float v0 = acc[mt][nt][half * 2 + 0] + b0;
                float v1 = acc[mt][nt][half * 2 + 1] + b1;
                if (EPI != 2) { v0 = fmaxf(v0, 0.0f); v1 = fmaxf(v1, 0.0f); }
                if (EPI == 0) {
                    *(float2*)(C + (size_t)r * Ncols + col) = make_float2(v0, v1);
                } else {
                    Oh[((size_t)r * Ncols + col) >> 1] = __floats2half2_rn(v0, v1);
                }
            }
        }
    }
}

// ===========================================================================
// fp32 GEMM (64x64) — tiny L4 (N=32)
// ===========================================================================
#define BM 64
#define BN 64
#define BK 16
__global__ __launch_bounds__(256)
void k_gemm(const float* __restrict__ A, const float* __restrict__ B,
            float* __restrict__ C, int M, int K, int N) {
    __shared__ float As[BK][BM + 4];
    __shared__ float Bs[BK][BN];
    const int block_row = blockIdx.y * BM;
    const int block_col = blockIdx.x * BN;
    const int tid = threadIdx.x;
    const int tr = (tid >> 4) << 2;
    const int tc = (tid & 15) << 2;
    float acc[4][4];
#pragma unroll
    for (int i = 0; i < 4; i++)
#pragma unroll
        for (int j = 0; j < 4; j++) acc[i][j] = 0.0f;
    for (int k0 = 0; k0 < K; k0 += BK) {
#pragma unroll
        for (int i = tid; i < BM * BK; i += 256) {
            int r = i >> 4, c = i & (BK - 1);
            int gr = block_row + r;
            As[c][r] = (gr < M) ? A[(size_t)gr * K + (k0 + c)] : 0.0f;
        }
#pragma unroll
        for (int i = tid; i < BK * BN; i += 256) {
            int r = i >> 6, c = i & (BN - 1);
            int gc = block_col + c;
            Bs[r][c] = (gc < N) ? B[(size_t)(k0 + r) * N + gc] : 0.0f;
        }
        __syncthreads();
#pragma unroll
        for (int k = 0; k < BK; ++k) {
            float a[4], b[4];
#pragma unroll
            for (int i = 0; i < 4; i++) a[i] = As[k][tr + i];
#pragma unroll
            for (int j = 0; j < 4; j++) b[j] = Bs[k][tc + j];
#pragma unroll
            for (int i = 0; i < 4; i++)
#pragma unroll
                for (int j = 0; j < 4; j++) acc[i][j] = fmaf(a[i], b[j], acc[i][j]);
        }
        __syncthreads();
    }
#pragma unroll
    for (int i = 0; i < 4; i++) {
        int gr = block_row + tr + i;
        if (gr >= M) continue;
#pragma unroll
        for (int j = 0; j < 4; j++) {
            int gc = block_col + tc + j;
            if (gc < N) C[(size_t)gr * N + gc] = acc[i][j];
        }
    }
}

// ===========================================================================
// Aggregations
// ===========================================================================
// fp16 in, H=512, block(128) per node; OUTMODE 0: fp16 out (no bias);
// OUTMODE 1: fp32 out + bias + relu
template <int OUTMODE>
__global__ __launch_bounds__(128)
void k_agg512_h(const uint2* __restrict__ lin,       // fp16 [N,512] as uint2(4h)
                const float* __restrict__ bias,
                float4* __restrict__ out32, __half2* __restrict__ outh) {
    const int node = blockIdx.x;
    const int tid = threadIdx.x;                      // 128 lanes of 4 halves
    float dii = g_dinv[node];
    float w0 = dii * dii;

    uint2 sv = lin[(size_t)node * 128 + tid];
    float2 f01 = __half22float2(*(const __half2*)&sv.x);
    float2 f23 = __half22float2(*(const __half2*)&sv.y);
    float a0 = f01.x * w0, a1 = f01.y * w0, a2 = f23.x * w0, a3 = f23.y * w0;

    __shared__ int   s_col[128];
    __shared__ float s_w[128];
    const int beg = g_rowptr[node];
    const int end = g_rowptr[node + 1];
    for (int j0 = beg; j0 < end; j0 += 128) {
        int n = min(128, end - j0);
        __syncthreads();
        if (tid < n) { s_col[tid] = g_col[j0 + tid]; s_w[tid] = g_wt[j0 + tid]; }
        __syncthreads();
        for (int j = 0; j < n; j++) {
            int s = s_col[j];
            float w = s_w[j];
            uint2 v = lin[(size_t)s * 128 + tid];
            float2 g01 = __half22float2(*(const __half2*)&v.x);
            float2 g23 = __half22float2(*(const __half2*)&v.y);
            a0 = fmaf(w, g01.x, a0); a1 = fmaf(w, g01.y, a1);
            a2 = fmaf(w, g23.x, a2); a3 = fmaf(w, g23.y, a3);
        }
    }
    if (OUTMODE == 1) {
        float4 b = reinterpret_cast<const float4*>(bias)[tid];
        float4 r;
        r.x = fmaxf(a0 + b.x, 0.0f); r.y = fmaxf(a1 + b.y, 0.0f);
        r.z = fmaxf(a2 + b.z, 0.0f); r.w = fmaxf(a3 + b.w, 0.0f);
        out32[(size_t)node * 128 + tid] = r;
    } else {
        size_t o = (size_t)node * 256 + tid * 2;
        outh[o]     = __floats2half2_rn(a0, a1);
        outh[o + 1] = __floats2half2_rn(a2, a3);
    }
}

// x [N,128] fp32 -> fp16 with aggregation; warp per node, 8 nodes/block
__global__ __launch_bounds__(256)
void k_agg128h(const float4* __restrict__ lin, __half2* __restrict__ oh) {
    int node = blockIdx.x * 8 + threadIdx.y;
    if (node >= N_NODES) return;
    int lane = threadIdx.x;
    float dii = g_dinv[node];
    float w0 = dii * dii;
    float4 a = lin[(size_t)node * 32 + lane];
    a.x *= w0; a.y *= w0; a.z *= w0; a.w *= w0;
    int beg = g_rowptr[node], end = g_rowptr[node + 1];
    for (int j = beg; j < end; j++) {
        int s = g_col[j];
        float w = g_wt[j];
        float4 v = lin[(size_t)s * 32 + lane];
        a.x = fmaf(w, v.x, a.x); a.y = fmaf(w, v.y, a.y);
        a.z = fmaf(w, v.z, a.z); a.w = fmaf(w, v.w, a.w);
    }
    size_t o = (size_t)node * 64 + lane * 2;
    oh[o]     = __floats2half2_rn(a.x, a.y);
    oh[o + 1] = __floats2half2_rn(a.z, a.w);
}

// L4 final: aggregate (H=32) + bias + log_softmax; warp per node
__global__ __launch_bounds__(256)
void k_agg_softmax32(const float* __restrict__ lin,
                     const float* __restrict__ bias,
                     float* __restrict__ out) {
    int node = blockIdx.x * 8 + threadIdx.y;
    if (node >= N_NODES) return;
    int lane = threadIdx.x;
    float dii = g_dinv[node];
    float v = lin[(size_t)node * 32 + lane] * dii * dii;
    int beg = g_rowptr[node], end = g_rowptr[node + 1];
    for (int j = beg; j < end; j++) {
        int s = g_col[j];
        float w = g_wt[j];
        v = fmaf(w, lin[(size_t)s * 32 + lane], v);
    }
    v += bias[lane];
    float m = v;
#pragma unroll
    for (int o = 16; o > 0; o >>= 1)
        m = fmaxf(m, __shfl_xor_sync(0xFFFFFFFFu, m, o));
    float ex = expf(v - m);
    float s = ex;
#pragma unroll
    for (int o = 16; o > 0; o >>= 1)
        s += __shfl_xor_sync(0xFFFFFFFFu, s, o);
    out[(size_t)node * 32 + lane] = v - m - logf(s);
}

// ===========================================================================
// Launch
// ===========================================================================
static inline int cdiv(long long a, int b) { return (int)((a + b - 1) / b); }

extern "C" void kernel_launch(void* const* d_in, const int* in_sizes, int n_in,
                              void* d_out, int out_size) {
    const float* x  = (const float*)d_in[0];
    const void*  ei = d_in[1];
    const float* W1 = (const float*)d_in[2];
    const float* b1 = (const float*)d_in[3];
    const float* W2 = (const float*)d_in[4];
    const float* b2 = (const float*)d_in[5];
    const float* W3 = (const float*)d_in[6];
    const float* b3 = (const float*)d_in[7];
    const float* W4 = (const float*)d_in[8];
    const float* b4 = (const float*)d_in[9];
    float* out = (float*)d_out;

    const int E = in_sizes[1] / 2;

    float4 *buf0, *buf1;
    uint4 *A, *A2, *Bh;
    cudaGetSymbolAddress((void**)&buf0, g_buf0);
    cudaGetSymbolAddress((void**)&buf1, g_buf1);
    cudaGetSymbolAddress((void**)&A, g_A);
    cudaGetSymbolAddress((void**)&A2, g_A2);
    cudaGetSymbolAddress((void**)&Bh, g_Bh);

    cudaFuncSetAttribute(k_gemm_mma<0>, cudaFuncAttributeMaxDynamicSharedMemorySize, GEMM_SMEM);
    cudaFuncSetAttribute(k_gemm_mma<1>, cudaFuncAttributeMaxDynamicSharedMemorySize, GEMM_SMEM);
    cudaFuncSetAttribute(k_gemm_mma<2>, cudaFuncAttributeMaxDynamicSharedMemorySize, GEMM_SMEM);

    const int MT = cdiv(N_NODES, 128);
    const __half* BW = (const __half*)Bh;

    // --- CSR + weights ---
    k_zero_detect<<<cdiv(N_NODES, 256), 256>>>(ei);
    k_convert_count<<<cdiv(E, 256), 256>>>(ei, E);
    k_scan_dinv<<<1, 1024>>>();
    k_fill<<<cdiv(E, 256), 256>>>(E);
    k_transT_all<<<1088, dim3(32, 8)>>>(W1, W2, W3, (__half*)Bh);

    // --- L1: agg(x)->fp16 (A2) -> GEMM K=128 N=512 bias+relu -> fp16 h1 (A) ---
    k_agg128h<<<cdiv(N_NODES, 8), dim3(32, 8)>>>((const float4*)x, (__half2*)A2);
    k_gemm_mma<1><<<dim3(H1_F / 128, MT), 256, GEMM_SMEM>>>(
        A2, BW + W1T_OFF, b1, nullptr, (__half2*)A, N_NODES, IN_F, H1_F);

    // --- L2: agg(h1)->fp16 (A2) -> GEMM K=512 N=1024 bias+relu -> fp16 h2 (A) ---
    k_agg512_h<0><<<N_NODES, 128>>>((const uint2*)A, nullptr, nullptr, (__half2*)A2);
    k_gemm_mma<1><<<dim3(H2_F / 128, MT), 256, GEMM_SMEM>>>(
        A2, BW + W2T_OFF, b2, nullptr, (__half2*)A, N_NODES, H1_F, H2_F);

    // --- L3: GEMM K=1024 N=512 raw -> fp16 lin3 (A2) -> agg+bias+relu -> buf1 ---
    k_gemm_mma<2><<<dim3(H3_F / 128, MT), 256, GEMM_SMEM>>>(
        A, BW + W3T_OFF, nullptr, nullptr, (__half2*)A2, N_NODES, H2_F, H3_F);
    k_agg512_h<1><<<N_NODES, 128>>>((const uint2*)A2, b3, buf1, nullptr);

    // --- L4: fp32 GEMM N=32 -> buf0 ; fused agg + bias + log_softmax ---
    {
        dim3 grid(1, cdiv(N_NODES, BM));
        k_gemm<<<grid, 256>>>((const float*)buf1, W4, (float*)buf0,
                              N_NODES, H3_F, OUT_F);
    }
    k_agg_softmax32<<<cdiv(N_NODES, 8), dim3(32, 8)>>>(
        (const float*)buf0, b4, out);
}

// round 10
// speedup vs baseline: 4.1489x; 1.1629x over previous
#include <cuda_runtime.h>
#include <cuda_fp16.h>
#include <math.h>
#include <stdint.h>

#define N_NODES 10000
#define E_EDGES 160000
#define IN_F    128
#define H1_F    512
#define H2_F    1024
#define H3_F    512
#define OUT_F   32

// Weight-transpose buffer offsets (fp16 elements)
#define W1T_OFF 0
#define W2T_OFF (IN_F * H1_F)
#define W3T_OFF (W2T_OFF + H1_F * H2_F)
#define W4T_OFF (W3T_OFF + H2_F * H3_F)
#define WT_TOTAL (W4T_OFF + H3_F * OUT_F)

// ===========================================================================
// Scratch (static device globals)
// ===========================================================================
__device__ int   g_is64;
__device__ int   g_src[E_EDGES];
__device__ int   g_dst[E_EDGES];
__device__ float g_dinv[N_NODES];
__device__ int   g_cnt[N_NODES];
__device__ int   g_cursor[N_NODES];
__device__ int   g_rowptr[N_NODES + 1];
__device__ int   g_col[E_EDGES];
__device__ float g_wt[E_EDGES];
__device__ float4 g_buf0[(size_t)N_NODES * OUT_F / 4];  // fp32 L4 lin
__device__ uint4 g_A[(size_t)N_NODES * H2_F * 2 / 16];  // fp16 activations A
__device__ uint4 g_A2[(size_t)N_NODES * H1_F * 2 / 16]; // fp16 activations B
__device__ uint4 g_Bh[(WT_TOTAL * 2 + 15) / 16];        // fp16 weights (T)

// ===========================================================================
// helpers
// ===========================================================================
__device__ __forceinline__ uint32_t smem_to_u32(const void* p) {
    uint32_t a;
    asm("{ .reg .u64 t; cvta.to.shared.u64 t, %1; cvt.u32.u64 %0, t; }"
        : "=r"(a) : "l"(p));
    return a;
}
__device__ __forceinline__ void cp_async16(uint32_t s, const void* g) {
    asm volatile("cp.async.cg.shared.global [%0], [%1], 16;"
                 :: "r"(s), "l"(__cvta_generic_to_global(g)) : "memory");
}
__device__ __forceinline__ void cp_commit() {
    asm volatile("cp.async.commit_group;" ::: "memory");
}
template <int NN>
__device__ __forceinline__ void cp_wait() {
    asm volatile("cp.async.wait_group %0;" :: "n"(NN) : "memory");
}
__device__ __forceinline__ void mma16816(float* c, const uint32_t* a,
                                         const uint32_t* b) {
    asm volatile(
        "mma.sync.aligned.m16n8k16.row.col.f32.f16.f16.f32 "
        "{%0,%1,%2,%3}, {%4,%5,%6,%7}, {%8,%9}, {%0,%1,%2,%3};"
        : "+f"(c[0]), "+f"(c[1]), "+f"(c[2]), "+f"(c[3])
        : "r"(a[0]), "r"(a[1]), "r"(a[2]), "r"(a[3]), "r"(b[0]), "r"(b[1]));
}

// ===========================================================================
// CSR chain
// ===========================================================================
__global__ void k_zero_detect(const void* __restrict__ ei) {
    int i = blockIdx.x * blockDim.x + threadIdx.x;
    if (i < N_NODES) { g_cnt[i] = 0; g_cursor[i] = 0; }
    if (blockIdx.x == 0) {
        if (threadIdx.x == 0) g_is64 = 1;
        __syncthreads();
        if (threadIdx.x < 128) {
            const long long* p = (const long long*)ei;
            long long v = p[threadIdx.x];
            if (v < 0 || v >= N_NODES) atomicAnd(&g_is64, 0);
        }
    }
}
__global__ void k_convert_count(const void* __restrict__ ei, int E) {
    int e = blockIdx.x * blockDim.x + threadIdx.x;
    if (e >= E) return;
    int s, d;
    if (g_is64) {
        const long long* p = (const long long*)ei;
        s = (int)p[e]; d = (int)p[e + E];
    } else {
        const int* p = (const int*)ei;
        s = p[e]; d = p[e + E];
    }
    g_src[e] = s; g_dst[e] = d;
    atomicAdd(&g_cnt[d], 1);
}
__global__ __launch_bounds__(1024)
void k_scan_dinv() {
    __shared__ int wsum[32];
    __shared__ int s_off;
    const int tid = threadIdx.x;
    const int lane = tid & 31;
    const int wid = tid >> 5;
    if (tid == 0) s_off = 0;
    __syncthreads();
    for (int base = 0; base < N_NODES; base += 1024) {
        int i = base + tid;
        int v = (i < N_NODES) ? g_cnt[i] : 0;
        if (i < N_NODES) g_dinv[i] = rsqrtf((float)v + 1.0f);
        int x = v;
#pragma unroll
        for (int o = 1; o < 32; o <<= 1) {
            int t = __shfl_up_sync(0xFFFFFFFFu, x, o);
            if (lane >= o) x += t;
        }
        if (lane == 31) wsum[wid] = x;
        __syncthreads();
        if (wid == 0) {
            int w = wsum[lane];
#pragma unroll
            for (int o = 1; o < 32; o <<= 1) {
                int t = __shfl_up_sync(0xFFFFFFFFu, w, o);
                if (lane >= o) w += t;
            }
            wsum[lane] = w;
        }
        __syncthreads();
        int incl = x + ((wid > 0) ? wsum[wid - 1] : 0);
        int off = s_off;
        if (i < N_NODES) g_rowptr[i + 1] = off + incl;
        __syncthreads();
        if (tid == 1023) s_off = off + incl;
        __syncthreads();
    }
    if (tid == 0) g_rowptr[0] = 0;
}
__global__ void k_fill(int E) {
    int e = blockIdx.x * blockDim.x + threadIdx.x;
    if (e >= E) return;
    int s = g_src[e];
    int d = g_dst[e];
    float w = g_dinv[s] * g_dinv[d];
    int pos = g_rowptr[d] + atomicAdd(&g_cursor[d], 1);
    g_col[pos] = s;
    g_wt[pos]  = w;
}

// ===========================================================================
// All-weights transpose + fp16: W[K,N] fp32 -> [N,K] fp16 (W1..W4)
// ===========================================================================
__global__ __launch_bounds__(256)
void k_transT_all(const float* __restrict__ W1, const float* __restrict__ W2,
                  const float* __restrict__ W3, const float* __restrict__ W4,
                  __half* __restrict__ hi) {
    const float* W; int K, N; size_t off;
    int b = blockIdx.x;
    if (b < 64)        { W = W1; K = IN_F; N = H1_F; off = W1T_OFF; }
    else if (b < 576)  { b -= 64;   W = W2; K = H1_F; N = H2_F; off = W2T_OFF; }
    else if (b < 1088) { b -= 576;  W = W3; K = H2_F; N = H3_F; off = W3T_OFF; }
    else               { b -= 1088; W = W4; K = H3_F; N = OUT_F; off = W4T_OFF; }
    int KT = K / 32;
    int k0 = (b % KT) * 32, n0 = (b / KT) * 32;

    __shared__ float t[32][33];
    int tx = threadIdx.x, ty = threadIdx.y;
#pragma unroll
    for (int j = 0; j < 4; j++)
        t[ty + j * 8][tx] = W[(size_t)(k0 + ty + j * 8) * N + (n0 + tx)];
    __syncthreads();
#pragma unroll
    for (int j = 0; j < 4; j++) {
        float v = t[tx][ty + j * 8];
        int n = n0 + ty + j * 8;
        int k = k0 + tx;
        hi[off + (size_t)n * K + k] = __float2half_rn(v);
    }
}

// ===========================================================================
// fp16 1-pass GEMM, 3-stage cp.async pipeline.
// A fp16 [M,K]; B fp16 [N,K] pre-T; fp32 acc. CTA 128x128, 8 warps 4mx2n.
// EPI: 0 bias+relu fp32 | 1 bias+relu fp16 | 2 raw fp16 | 3 raw fp32
// NG:  bounds-guard B rows / C cols against Ncols (for Ncols < 128)
// ===========================================================================
#define KC 32
#define SROW 40                      // fp16 row stride (80 B)
#define TILE_B (128 * SROW * 2)      // 10240 B
#define STAGE_B (2 * TILE_B)         // 20480 B (A, B)
#define GEMM_SMEM (3 * STAGE_B)      // 61440 B

template <int EPI, bool NG>
__global__ __launch_bounds__(256)
void k_gemm_mma(const uint4* __restrict__ A, const __half* __restrict__ B,
                const float* __restrict__ bias, float* __restrict__ C,
                __half2* __restrict__ Oh,
                int M, int K, int Ncols) {
    extern __shared__ char sm[];
    const uint32_t smb = smem_to_u32(sm);
    const int tid = threadIdx.x;
    const int lane = tid & 31;
    const int wid = tid >> 5;
    const int warp_m = wid & 3;
    const int warp_n = wid >> 2;
    const int g = lane >> 2;
    const int tig = lane & 3;
    const int mrow0 = blockIdx.y * 128;
    const int ncol0 = blockIdx.x * 128;
    const int KU = K >> 3;
    const int nChunks = K / KC;

    float acc[2][8][4];
#pragma unroll
    for (int i = 0; i < 2; i++)
#pragma unroll
        for (int j = 0; j < 8; j++)
#pragma unroll
            for (int q = 0; q < 4; q++) acc[i][j][q] = 0.0f;

    auto load_chunk = [&](int it, int st) {
        const int ku0 = it * (KC / 8);
        const uint32_t sb = smb + st * STAGE_B;
#pragma unroll
        for (int q = tid; q < 512; q += 256) {
            int row = q >> 2;
            int cb = q & 3;
            uint32_t so = (uint32_t)(row * 80 + cb * 16);
            int gm = mrow0 + row;
            if (gm < M) {
                cp_async16(sb + so, A + (size_t)gm * KU + ku0 + cb);
            } else {
                *(uint4*)(sm + st * STAGE_B + so) = make_uint4(0, 0, 0, 0);
            }
            int brow = ncol0 + row;
            if (!NG || brow < Ncols) {
                size_t bb = (size_t)brow * K + it * KC + cb * 8;
                cp_async16(sb + TILE_B + so, B + bb);
            } else {
                *(uint4*)(sm + st * STAGE_B + TILE_B + so) = make_uint4(0, 0, 0, 0);
            }
        }
        cp_commit();
    };

    load_chunk(0, 0);
    load_chunk(1, 1);
    for (int it = 0; it < nChunks; it++) {
        const int cur = it % 3;
        if (it + 2 < nChunks) {
            load_chunk(it + 2, (it + 2) % 3);
            cp_wait<2>();
        } else if (it + 1 < nChunks) {
            cp_wait<1>();
        } else {
            cp_wait<0>();
        }
        __syncthreads();

        const __half* sA = (const __half*)(sm + cur * STAGE_B);
        const __half* sB = (const __half*)(sm + cur * STAGE_B + TILE_B);

#pragma unroll
        for (int ks = 0; ks < KC / 16; ks++) {
            const int k0 = ks * 16;
            uint32_t ah[2][4];
#pragma unroll
            for (int mt = 0; mt < 2; mt++) {
                int r0 = warp_m * 32 + mt * 16 + g;
                int c0 = k0 + tig * 2;
                ah[mt][0] = *(const uint32_t*)(sA + r0 * SROW + c0);
                ah[mt][1] = *(const uint32_t*)(sA + (r0 + 8) * SROW + c0);
                ah[mt][2] = *(const uint32_t*)(sA + r0 * SROW + c0 + 8);
                ah[mt][3] = *(const uint32_t*)(sA + (r0 + 8) * SROW + c0 + 8);
            }
            uint32_t bh[8][2];
#pragma unroll
            for (int nt = 0; nt < 8; nt++) {
                int r0 = warp_n * 64 + nt * 8 + g;
                int c0 = k0 + tig * 2;
                bh[nt][0] = *(const uint32_t*)(sB + r0 * SROW + c0);
                bh[nt][1] = *(const uint32_t*)(sB + r0 * SROW + c0 + 8);
            }
#pragma unroll
            for (int mt = 0; mt < 2; mt++)
#pragma unroll
                for (int nt = 0; nt < 8; nt++) mma16816(acc[mt][nt], ah[mt], bh[nt]);
        }
        __syncthreads();
    }

    // Epilogue
#pragma unroll
    for (int mt = 0; mt < 2; mt++) {
        int rbase = mrow0 + warp_m * 32 + mt * 16;
#pragma unroll
        for (int nt = 0; nt < 8; nt++) {
            int col = ncol0 + warp_n * 64 + nt * 8 + tig * 2;
            if (NG && col >= Ncols) continue;
            float b0 = 0.0f, b1 = 0.0f;
            if (EPI == 0 || EPI == 1) { b0 = bias[col]; b1 = bias[col + 1]; }
#pragma unroll
            for (int half = 0; half < 2; half++) {
                int r = rbase + g + half * 8;
                if (r >= M) continue;
                float v0 = acc[mt][nt][half * 2 + 0] + b0;
                float v1 = acc[mt][nt][half * 2 + 1] + b1;
                if (EPI == 0 || EPI == 1) { v0 = fmaxf(v0, 0.0f); v1 = fmaxf(v1, 0.0f); }
                if (EPI == 0 || EPI == 3) {
                    *(float2*)(C + (size_t)r * Ncols + col) = make_float2(v0, v1);
                } else {
                    Oh[((size_t)r * Ncols + col) >> 1] = __floats2half2_rn(v0, v1);
                }
            }
        }
    }
}

// ===========================================================================
// Aggregations
// ===========================================================================
// fp16 in, H=512, block(128) per node.
// OUTMODE 0: fp16 out (no bias) | OUTMODE 2: bias+relu -> fp16 out
template <int OUTMODE>
__global__ __launch_bounds__(128)
void k_agg512_h(const uint2* __restrict__ lin,       // fp16 [N,512] as uint2
                const float* __restrict__ bias,
                __half2* __restrict__ outh) {
    const int node = blockIdx.x;
    const int tid = threadIdx.x;
    float dii = g_dinv[node];
    float w0 = dii * dii;

    uint2 sv = lin[(size_t)node * 128 + tid];
    float2 f01 = __half22float2(*(const __half2*)&sv.x);
    float2 f23 = __half22float2(*(const __half2*)&sv.y);
    float a0 = f01.x * w0, a1 = f01.y * w0, a2 = f23.x * w0, a3 = f23.y * w0;

    __shared__ int   s_col[128];
    __shared__ float s_w[128];
    const int beg = g_rowptr[node];
    const int end = g_rowptr[node + 1];
    for (int j0 = beg; j0 < end; j0 += 128) {
        int n = min(128, end - j0);
        __syncthreads();
        if (tid < n) { s_col[tid] = g_col[j0 + tid]; s_w[tid] = g_wt[j0 + tid]; }
        __syncthreads();
        for (int j = 0; j < n; j++) {
            int s = s_col[j];
            float w = s_w[j];
            uint2 v = lin[(size_t)s * 128 + tid];
            float2 g01 = __half22float2(*(const __half2*)&v.x);
            float2 g23 = __half22float2(*(const __half2*)&v.y);
            a0 = fmaf(w, g01.x, a0); a1 = fmaf(w, g01.y, a1);
            a2 = fmaf(w, g23.x, a2); a3 = fmaf(w, g23.y, a3);
        }
    }
    if (OUTMODE == 2) {
        float4 b = reinterpret_cast<const float4*>(bias)[tid];
        a0 = fmaxf(a0 + b.x, 0.0f); a1 = fmaxf(a1 + b.y, 0.0f);
        a2 = fmaxf(a2 + b.z, 0.0f); a3 = fmaxf(a3 + b.w, 0.0f);
    }
    size_t o = (size_t)node * 256 + tid * 2;
    outh[o]     = __floats2half2_rn(a0, a1);
    outh[o + 1] = __floats2half2_rn(a2, a3);
}

// x [N,128] fp32 -> fp16 with aggregation; warp per node, 8 nodes/block
__global__ __launch_bounds__(256)
void k_agg128h(const float4* __restrict__ lin, __half2* __restrict__ oh) {
    int node = blockIdx.x * 8 + threadIdx.y;
    if (node >= N_NODES) return;
    int lane = threadIdx.x;
    float dii = g_dinv[node];
    float w0 = dii * dii;
    float4 a = lin[(size_t)node * 32 + lane];
    a.x *= w0; a.y *= w0; a.z *= w0; a.w *= w0;
    int beg = g_rowptr[node], end = g_rowptr[node + 1];
    for (int j = beg; j < end; j++) {
        int s = g_col[j];
        float w = g_wt[j];
        float4 v = lin[(size_t)s * 32 + lane];
        a.x = fmaf(w, v.x, a.x); a.y = fmaf(w, v.y, a.y);
        a.z = fmaf(w, v.z, a.z); a.w = fmaf(w, v.w, a.w);
    }
    size_t o = (size_t)node * 64 + lane * 2;
    oh[o]     = __floats2half2_rn(a.x, a.y);
    oh[o + 1] = __floats2half2_rn(a.z, a.w);
}

// L4 final: aggregate (H=32, fp32 lin) + bias + log_softmax; warp per node
__global__ __launch_bounds__(256)
void k_agg_softmax32(const float* __restrict__ lin,
                     const float* __restrict__ bias,
                     float* __restrict__ out) {
    int node = blockIdx.x * 8 + threadIdx.y;
    if (node >= N_NODES) return;
    int lane = threadIdx.x;
    float dii = g_dinv[node];
    float v = lin[(size_t)node * 32 + lane] * dii * dii;
    int beg = g_rowptr[node], end = g_rowptr[node + 1];
    for (int j = beg; j < end; j++) {
        int s = g_col[j];
        float w = g_wt[j];
        v = fmaf(w, lin[(size_t)s * 32 + lane], v);
    }
    v += bias[lane];
    float m = v;
#pragma unroll
    for (int o = 16; o > 0; o >>= 1)
        m = fmaxf(m, __shfl_xor_sync(0xFFFFFFFFu, m, o));
    float ex = expf(v - m);
    float s = ex;
#pragma unroll
    for (int o = 16; o > 0; o >>= 1)
        s += __shfl_xor_sync(0xFFFFFFFFu, s, o);
    out[(size_t)node * 32 + lane] = v - m - logf(s);
}

// ===========================================================================
// Launch
// ===========================================================================
static inline int cdiv(long long a, int b) { return (int)((a + b - 1) / b); }

extern "C" void kernel_launch(void* const* d_in, const int* in_sizes, int n_in,
                              void* d_out, int out_size) {
    const float* x  = (const float*)d_in[0];
    const void*  ei = d_in[1];
    const float* W1 = (const float*)d_in[2];
    const float* b1 = (const float*)d_in[3];
    const float* W2 = (const float*)d_in[4];
    const float* b2 = (const float*)d_in[5];
    const float* W3 = (const float*)d_in[6];
    const float* b3 = (const float*)d_in[7];
    const float* W4 = (const float*)d_in[8];
    const float* b4 = (const float*)d_in[9];
    float* out = (float*)d_out;

    const int E = in_sizes[1] / 2;

    float4 *buf0;
    uint4 *A, *A2, *Bh;
    cudaGetSymbolAddress((void**)&buf0, g_buf0);
    cudaGetSymbolAddress((void**)&A, g_A);
    cudaGetSymbolAddress((void**)&A2, g_A2);
    cudaGetSymbolAddress((void**)&Bh, g_Bh);

    cudaFuncSetAttribute((const void*)k_gemm_mma<1, false>,
                         cudaFuncAttributeMaxDynamicSharedMemorySize, GEMM_SMEM);
    cudaFuncSetAttribute((const void*)k_gemm_mma<2, false>,
                         cudaFuncAttributeMaxDynamicSharedMemorySize, GEMM_SMEM);
    cudaFuncSetAttribute((const void*)k_gemm_mma<3, true>,
                         cudaFuncAttributeMaxDynamicSharedMemorySize, GEMM_SMEM);

    const int MT = cdiv(N_NODES, 128);
    const __half* BW = (const __half*)Bh;

    // --- CSR + weights ---
    k_zero_detect<<<cdiv(N_NODES, 256), 256>>>(ei);
    k_convert_count<<<cdiv(E, 256), 256>>>(ei, E);
    k_scan_dinv<<<1, 1024>>>();
    k_fill<<<cdiv(E, 256), 256>>>(E);
    k_transT_all<<<1104, dim3(32, 8)>>>(W1, W2, W3, W4, (__half*)Bh);

    // --- L1: agg(x)->fp16 (A2) -> GEMM K=128 N=512 bias+relu -> fp16 h1 (A) ---
    k_agg128h<<<cdiv(N_NODES, 8), dim3(32, 8)>>>((const float4*)x, (__half2*)A2);
    k_gemm_mma<1, false><<<dim3(H1_F / 128, MT), 256, GEMM_SMEM>>>(
        A2, BW + W1T_OFF, b1, nullptr, (__half2*)A, N_NODES, IN_F, H1_F);

    // --- L2: agg(h1)->fp16 (A2) -> GEMM K=512 N=1024 bias+relu -> fp16 h2 (A) ---
    k_agg512_h<0><<<N_NODES, 128>>>((const uint2*)A, nullptr, (__half2*)A2);
    k_gemm_mma<1, false><<<dim3(H2_F / 128, MT), 256, GEMM_SMEM>>>(
        A2, BW + W2T_OFF, b2, nullptr, (__half2*)A, N_NODES, H1_F, H2_F);

    // --- L3: GEMM K=1024 N=512 raw fp16 (A2) -> agg+bias+relu -> fp16 h3 (A) ---
    k_gemm_mma<2, false><<<dim3(H3_F / 128, MT), 256, GEMM_SMEM>>>(
        A, BW + W3T_OFF, nullptr, nullptr, (__half2*)A2, N_NODES, H2_F, H3_F);
    k_agg512_h<2><<<N_NODES, 128>>>((const uint2*)A2, b3, (__half2*)A);

    // --- L4: fp16 MMA GEMM K=512 N=32 raw fp32 -> buf0 ; agg+bias+softmax ---
    k_gemm_mma<3, true><<<dim3(1, MT), 256, GEMM_SMEM>>>(
        A, BW + W4T_OFF, nullptr, (float*)buf0, nullptr, N_NODES, H3_F, OUT_F);
    k_agg_softmax32<<<cdiv(N_NODES, 8), dim3(32, 8)>>>(
        (const float*)buf0, b4, out);
}